// round 2
// baseline (speedup 1.0000x reference)
#include <cuda_runtime.h>
#include <cuda_bf16.h>
#include <math.h>

#define S_LEN 4096
#define HID   2048
#define NH    16
#define NKV   4
#define HD    128
#define KVDIM (NKV * HD)   // 512

// -------- scratch (no allocs allowed) --------
__device__ float g_Q[S_LEN * HID];      // [s][h*128+d]
__device__ float g_K[S_LEN * KVDIM];    // [s][kvh*128+d]
__device__ float g_V[S_LEN * KVDIM];
__device__ float g_AO[S_LEN * HID];     // attention output [s][h*128+d]

// ============================================================
// Tiled NT GEMM: C[m,n] = sum_k A[m,k]*B[n,k] + bias[n]
// BM=BN=64, BK=16, 256 threads, 4x4 microtile per thread.
// M,N multiples of 64; K multiple of 16.
// ============================================================
__global__ __launch_bounds__(256) void gemm_nt_kernel(
    const float* __restrict__ A, const float* __restrict__ B,
    const float* __restrict__ bias, float* __restrict__ C,
    int M, int N, int K, int lda, int ldb, int ldc)
{
    __shared__ __align__(16) float As[16][64];   // [k][m]
    __shared__ __align__(16) float Bs[16][64];   // [k][n]

    const int tid = threadIdx.x;
    const int tx = tid & 15;        // n group
    const int ty = tid >> 4;        // m group
    const int row0 = blockIdx.y * 64;
    const int col0 = blockIdx.x * 64;

    const int lr = tid >> 2;          // 0..63 row within tile
    const int lc = (tid & 3) << 2;    // 0,4,8,12 k-offset
    const float* Ag = A + (size_t)(row0 + lr) * lda + lc;
    const float* Bg = B + (size_t)(col0 + lr) * ldb + lc;

    float acc[4][4];
#pragma unroll
    for (int i = 0; i < 4; ++i)
#pragma unroll
        for (int j = 0; j < 4; ++j) acc[i][j] = 0.0f;

    for (int k0 = 0; k0 < K; k0 += 16) {
        float4 av = *(const float4*)(Ag + k0);
        float4 bv = *(const float4*)(Bg + k0);
        As[lc + 0][lr] = av.x; As[lc + 1][lr] = av.y;
        As[lc + 2][lr] = av.z; As[lc + 3][lr] = av.w;
        Bs[lc + 0][lr] = bv.x; Bs[lc + 1][lr] = bv.y;
        Bs[lc + 2][lr] = bv.z; Bs[lc + 3][lr] = bv.w;
        __syncthreads();
#pragma unroll
        for (int k = 0; k < 16; ++k) {
            float4 a = *(const float4*)&As[k][ty << 2];
            float4 b = *(const float4*)&Bs[k][tx << 2];
            acc[0][0] += a.x * b.x; acc[0][1] += a.x * b.y;
            acc[0][2] += a.x * b.z; acc[0][3] += a.x * b.w;
            acc[1][0] += a.y * b.x; acc[1][1] += a.y * b.y;
            acc[1][2] += a.y * b.z; acc[1][3] += a.y * b.w;
            acc[2][0] += a.z * b.x; acc[2][1] += a.z * b.y;
            acc[2][2] += a.z * b.z; acc[2][3] += a.z * b.w;
            acc[3][0] += a.w * b.x; acc[3][1] += a.w * b.y;
            acc[3][2] += a.w * b.z; acc[3][3] += a.w * b.w;
        }
        __syncthreads();
    }

    float b0 = 0.f, b1 = 0.f, b2 = 0.f, b3 = 0.f;
    if (bias) {
        const float* bp = bias + col0 + (tx << 2);
        b0 = bp[0]; b1 = bp[1]; b2 = bp[2]; b3 = bp[3];
    }
#pragma unroll
    for (int i = 0; i < 4; ++i) {
        int row = row0 + (ty << 2) + i;
        float4 o = make_float4(acc[i][0] + b0, acc[i][1] + b1,
                               acc[i][2] + b2, acc[i][3] + b3);
        *(float4*)&C[(size_t)row * ldc + col0 + (tx << 2)] = o;
    }
}

// ============================================================
// RoPE (in place on Q and K). One block per token.
// Double-precision range reduction keeps accuracy even if
// fast-math maps sinf/cosf to the low-accuracy intrinsics.
// ============================================================
__global__ void rope_kernel(float* __restrict__ Q, float* __restrict__ K)
{
    const int s = blockIdx.x;
    const int total = (NH + NKV) * 64;   // pairs per token
    for (int p = threadIdx.x; p < total; p += blockDim.x) {
        float* base;
        int d;
        if (p < NH * 64) {
            base = Q + (size_t)s * HID + (p >> 6) * HD;
            d = p & 63;
        } else {
            int p2 = p - NH * 64;
            base = K + (size_t)s * KVDIM + (p2 >> 6) * HD;
            d = p2 & 63;
        }
        float inv = powf(10000.0f, -(float)(2 * d) * (1.0f / 128.0f));
        float ang = (float)s * inv;                  // matches reference f32 product
        double da = (double)ang;
        const double twopi = 6.283185307179586;
        da -= floor(da / twopi) * twopi;             // exact-enough reduction
        float r = (float)da;
        float c = cosf(r), sn = sinf(r);
        float x0 = base[d], x1 = base[d + 64];
        base[d]      = x0 * c - x1 * sn;
        base[d + 64] = x1 * c + x0 * sn;
    }
}

// ============================================================
// Flash attention, fp32, causal, GQA (4 Q heads share 1 KV head).
// 64x64 tiles, 256 threads: thread (tx,ty) owns 4 q-rows (ty) and
// 4 k-cols (tx) for scores; 4 q-rows x 8 out-cols for O.
// Per-row m/l live in registers (replicated across the 16-lane
// row group, maintained with shuffle reductions).
// ============================================================
#define QROWPAD 132
#define PPAD    68

__global__ __launch_bounds__(256, 1) void flash_kernel(
    const float* __restrict__ Q, const float* __restrict__ K,
    const float* __restrict__ V, float* __restrict__ Out)
{
    extern __shared__ float sm[];
    float* Qs = sm;                       // [64][132]
    float* Ks = sm + 64 * QROWPAD;        // [64][132]
    float* Vs = sm + 2 * 64 * QROWPAD;    // [64][132]
    float* Ps = sm + 3 * 64 * QROWPAD;    // [64][68]

    const int h   = blockIdx.y;
    const int qt  = (int)gridDim.x - 1 - (int)blockIdx.x;  // heavy blocks first
    const int kvh = h >> 2;
    const int tid = threadIdx.x;
    const int tx  = tid & 15;
    const int ty  = tid >> 4;

    const int lr = tid >> 2;              // 0..63
    const int lc = (tid & 3) * 32;        // float offset within 128-wide row

    // load Q tile
    {
        const float* qg = Q + (size_t)(qt * 64 + lr) * HID + h * HD + lc;
        float* qs = &Qs[lr * QROWPAD + lc];
#pragma unroll
        for (int i = 0; i < 8; ++i)
            *(float4*)(qs + i * 4) = *(const float4*)(qg + i * 4);
    }

    float m[4], l[4], o[4][8];
#pragma unroll
    for (int i = 0; i < 4; ++i) {
        m[i] = -1e30f; l[i] = 0.0f;
#pragma unroll
        for (int c = 0; c < 8; ++c) o[i][c] = 0.0f;
    }
    const float scale = 0.08838834764831843f;  // 1/sqrt(128)

    for (int kt = 0; kt <= qt; ++kt) {
        // load K,V tiles
        {
            const float* kg = K + (size_t)(kt * 64 + lr) * KVDIM + kvh * HD + lc;
            const float* vg = V + (size_t)(kt * 64 + lr) * KVDIM + kvh * HD + lc;
            float* ks = &Ks[lr * QROWPAD + lc];
            float* vs = &Vs[lr * QROWPAD + lc];
#pragma unroll
            for (int i = 0; i < 8; ++i) {
                *(float4*)(ks + i * 4) = *(const float4*)(kg + i * 4);
                *(float4*)(vs + i * 4) = *(const float4*)(vg + i * 4);
            }
        }
        __syncthreads();

        // ---- scores: S = Q K^T ----
        float sacc[4][4];
#pragma unroll
        for (int i = 0; i < 4; ++i)
#pragma unroll
            for (int j = 0; j < 4; ++j) sacc[i][j] = 0.0f;

#pragma unroll 4
        for (int d4 = 0; d4 < 32; ++d4) {
            float4 a0 = *(const float4*)&Qs[(ty * 4 + 0) * QROWPAD + d4 * 4];
            float4 a1 = *(const float4*)&Qs[(ty * 4 + 1) * QROWPAD + d4 * 4];
            float4 a2 = *(const float4*)&Qs[(ty * 4 + 2) * QROWPAD + d4 * 4];
            float4 a3 = *(const float4*)&Qs[(ty * 4 + 3) * QROWPAD + d4 * 4];
            float4 b0 = *(const float4*)&Ks[(tx * 4 + 0) * QROWPAD + d4 * 4];
            float4 b1 = *(const float4*)&Ks[(tx * 4 + 1) * QROWPAD + d4 * 4];
            float4 b2 = *(const float4*)&Ks[(tx * 4 + 2) * QROWPAD + d4 * 4];
            float4 b3 = *(const float4*)&Ks[(tx * 4 + 3) * QROWPAD + d4 * 4];
#define DOT(i, j, A, B) \
            sacc[i][j] += A.x * B.x; sacc[i][j] += A.y * B.y; \
            sacc[i][j] += A.z * B.z; sacc[i][j] += A.w * B.w;
            DOT(0,0,a0,b0) DOT(0,1,a0,b1) DOT(0,2,a0,b2) DOT(0,3,a0,b3)
            DOT(1,0,a1,b0) DOT(1,1,a1,b1) DOT(1,2,a1,b2) DOT(1,3,a1,b3)
            DOT(2,0,a2,b0) DOT(2,1,a2,b1) DOT(2,2,a2,b2) DOT(2,3,a2,b3)
            DOT(3,0,a3,b0) DOT(3,1,a3,b1) DOT(3,2,a3,b2) DOT(3,3,a3,b3)
#undef DOT
        }

        // ---- scale + causal mask + online softmax ----
        float mt[4];
#pragma unroll
        for (int i = 0; i < 4; ++i) {
            int qrow = qt * 64 + ty * 4 + i;
#pragma unroll
            for (int j = 0; j < 4; ++j) {
                float s = sacc[i][j] * scale;
                if (kt == qt && (kt * 64 + tx * 4 + j) > qrow) s = -1e30f;
                sacc[i][j] = s;
            }
            mt[i] = fmaxf(fmaxf(sacc[i][0], sacc[i][1]),
                          fmaxf(sacc[i][2], sacc[i][3]));
        }
#pragma unroll
        for (int off = 1; off < 16; off <<= 1) {
#pragma unroll
            for (int i = 0; i < 4; ++i)
                mt[i] = fmaxf(mt[i], __shfl_xor_sync(0xffffffffu, mt[i], off));
        }

        float corr[4], rs[4];
#pragma unroll
        for (int i = 0; i < 4; ++i) {
            float mn = fmaxf(m[i], mt[i]);
            corr[i] = expf(m[i] - mn);
            m[i] = mn;
            float p0 = expf(sacc[i][0] - mn);
            float p1 = expf(sacc[i][1] - mn);
            float p2 = expf(sacc[i][2] - mn);
            float p3 = expf(sacc[i][3] - mn);
            float* pr = &Ps[(ty * 4 + i) * PPAD + tx * 4];
            pr[0] = p0; pr[1] = p1; pr[2] = p2; pr[3] = p3;
            rs[i] = (p0 + p1) + (p2 + p3);
        }
#pragma unroll
        for (int off = 1; off < 16; off <<= 1) {
#pragma unroll
            for (int i = 0; i < 4; ++i)
                rs[i] += __shfl_xor_sync(0xffffffffu, rs[i], off);
        }
#pragma unroll
        for (int i = 0; i < 4; ++i) {
            l[i] = l[i] * corr[i] + rs[i];
#pragma unroll
            for (int c = 0; c < 8; ++c) o[i][c] *= corr[i];
        }
        __syncthreads();   // Ps fully written; K tile reads done

        // ---- O += P V ----
#pragma unroll 4
        for (int kk = 0; kk < 64; ++kk) {
            float4 v0 = *(const float4*)&Vs[kk * QROWPAD + tx * 8];
            float4 v1 = *(const float4*)&Vs[kk * QROWPAD + tx * 8 + 4];
#pragma unroll
            for (int i = 0; i < 4; ++i) {
                float p = Ps[(ty * 4 + i) * PPAD + kk];
                o[i][0] += p * v0.x; o[i][1] += p * v0.y;
                o[i][2] += p * v0.z; o[i][3] += p * v0.w;
                o[i][4] += p * v1.x; o[i][5] += p * v1.y;
                o[i][6] += p * v1.z; o[i][7] += p * v1.w;
            }
        }
        __syncthreads();   // done with Vs/Ps before next tile overwrites
    }

    // ---- epilogue ----
#pragma unroll
    for (int i = 0; i < 4; ++i) {
        float inv = 1.0f / l[i];
        int row = qt * 64 + ty * 4 + i;
        float* op = Out + (size_t)row * HID + h * HD + tx * 8;
        float4 r0 = make_float4(o[i][0] * inv, o[i][1] * inv,
                                o[i][2] * inv, o[i][3] * inv);
        float4 r1 = make_float4(o[i][4] * inv, o[i][5] * inv,
                                o[i][6] * inv, o[i][7] * inv);
        *(float4*)op = r0;
        *(float4*)(op + 4) = r1;
    }
}

// ============================================================
// launch
// ============================================================
extern "C" void kernel_launch(void* const* d_in, const int* in_sizes, int n_in,
                              void* d_out, int out_size)
{
    const float* hidden = (const float*)d_in[0];
    // d_in[1] = attention_mask: exactly causal, applied analytically -> unused
    const float* q_w = (const float*)d_in[2];
    const float* q_b = (const float*)d_in[3];
    const float* k_w = (const float*)d_in[4];
    const float* k_b = (const float*)d_in[5];
    const float* v_w = (const float*)d_in[6];
    const float* v_b = (const float*)d_in[7];
    const float* o_w = (const float*)d_in[8];
    float* out = (float*)d_out;

    float *Qp, *Kp, *Vp, *AOp;
    cudaGetSymbolAddress((void**)&Qp,  g_Q);
    cudaGetSymbolAddress((void**)&Kp,  g_K);
    cudaGetSymbolAddress((void**)&Vp,  g_V);
    cudaGetSymbolAddress((void**)&AOp, g_AO);

    dim3 blk(256);

    // Q/K/V projections
    gemm_nt_kernel<<<dim3(HID / 64, S_LEN / 64), blk>>>(
        hidden, q_w, q_b, Qp, S_LEN, HID, HID, HID, HID, HID);
    gemm_nt_kernel<<<dim3(KVDIM / 64, S_LEN / 64), blk>>>(
        hidden, k_w, k_b, Kp, S_LEN, KVDIM, HID, HID, HID, KVDIM);
    gemm_nt_kernel<<<dim3(KVDIM / 64, S_LEN / 64), blk>>>(
        hidden, v_w, v_b, Vp, S_LEN, KVDIM, HID, HID, HID, KVDIM);

    // RoPE in place on Q, K
    rope_kernel<<<S_LEN, 256>>>(Qp, Kp);

    // flash attention
    int smem = (3 * 64 * QROWPAD + 64 * PPAD) * (int)sizeof(float);
    cudaFuncSetAttribute(flash_kernel,
                         cudaFuncAttributeMaxDynamicSharedMemorySize, smem);
    flash_kernel<<<dim3(64, NH), blk, smem>>>(Qp, Kp, Vp, AOp);

    // output projection
    gemm_nt_kernel<<<dim3(HID / 64, S_LEN / 64), blk>>>(
        AOp, o_w, nullptr, out, S_LEN, HID, HID, HID, HID, HID);
}

// round 3
// speedup vs baseline: 3.0451x; 3.0451x over previous
#include <cuda_runtime.h>
#include <cuda_bf16.h>
#include <math.h>

#define S_LEN 4096
#define HID   2048
#define NH    16
#define NKV   4
#define HD    128
#define KVDIM (NKV * HD)   // 512

// -------- scratch (no allocs allowed) --------
__device__ float g_Q[S_LEN * HID];
__device__ float g_K[S_LEN * KVDIM];
__device__ float g_V[S_LEN * KVDIM];
__device__ float g_AO[S_LEN * HID];
__device__ float g_cos[S_LEN * 64];
__device__ float g_sin[S_LEN * 64];

// ---------- tf32 helpers ----------
__device__ __forceinline__ float f2tf(float x) {
    unsigned u;
    asm("cvt.rna.tf32.f32 %0, %1;" : "=r"(u) : "f"(x));
    return __uint_as_float(u);
}

__device__ __forceinline__ void mma_tf32(float* c,
    unsigned a0, unsigned a1, unsigned a2, unsigned a3,
    unsigned b0, unsigned b1)
{
    asm volatile(
        "mma.sync.aligned.m16n8k8.row.col.f32.tf32.tf32.f32 "
        "{%0,%1,%2,%3}, {%4,%5,%6,%7}, {%8,%9}, {%0,%1,%2,%3};\n"
        : "+f"(c[0]), "+f"(c[1]), "+f"(c[2]), "+f"(c[3])
        : "r"(a0), "r"(a1), "r"(a2), "r"(a3), "r"(b0), "r"(b1));
}

// ============================================================
// tf32 tensor-core NT GEMM: C[m,n] = sum_k A[m,k]*B[n,k] + bias[n]
// Block tile 128x64, BK=32, 256 threads (8 warps, 4x2 grid of
// 32x32 warp tiles). Fragment LDS is bank-conflict-free (ld=36).
// ============================================================
#define GLD 36
__global__ __launch_bounds__(256) void gemm_tf32(
    const float* __restrict__ A, const float* __restrict__ B,
    const float* __restrict__ bias, float* __restrict__ C,
    int M, int N, int K)
{
    __shared__ float As[128 * GLD];   // [m][k]
    __shared__ float Bs[64 * GLD];    // [n][k]

    const int tid  = threadIdx.x;
    const int warp = tid >> 5, lane = tid & 31;
    const int gid  = lane >> 2, tig = lane & 3;
    const int rbase = (warp & 3) * 32;
    const int cbase = (warp >> 2) * 32;
    const int row0 = blockIdx.y * 128;
    const int col0 = blockIdx.x * 64;

    float acc[2][4][4];
#pragma unroll
    for (int mi = 0; mi < 2; ++mi)
#pragma unroll
        for (int ni = 0; ni < 4; ++ni)
#pragma unroll
            for (int j = 0; j < 4; ++j) acc[mi][ni][j] = 0.0f;

    const int ar = tid >> 1, akc = (tid & 1) * 16;
    const int br = tid >> 2, bkc = (tid & 3) * 8;
    const float* Ag = A + (size_t)(row0 + ar) * K + akc;
    const float* Bg = B + (size_t)(col0 + br) * K + bkc;

    for (int k0 = 0; k0 < K; k0 += 32) {
#pragma unroll
        for (int i = 0; i < 4; ++i) {
            float4 v = *(const float4*)(Ag + k0 + 4 * i);
            float* d = &As[ar * GLD + akc + 4 * i];
            d[0] = f2tf(v.x); d[1] = f2tf(v.y);
            d[2] = f2tf(v.z); d[3] = f2tf(v.w);
        }
#pragma unroll
        for (int i = 0; i < 2; ++i) {
            float4 v = *(const float4*)(Bg + k0 + 4 * i);
            float* d = &Bs[br * GLD + bkc + 4 * i];
            d[0] = f2tf(v.x); d[1] = f2tf(v.y);
            d[2] = f2tf(v.z); d[3] = f2tf(v.w);
        }
        __syncthreads();
#pragma unroll
        for (int ks = 0; ks < 4; ++ks) {
            const int kk = ks * 8 + tig;
            unsigned a[2][4];
#pragma unroll
            for (int mi = 0; mi < 2; ++mi) {
                const int r = rbase + 16 * mi + gid;
                a[mi][0] = __float_as_uint(As[r * GLD + kk]);
                a[mi][1] = __float_as_uint(As[(r + 8) * GLD + kk]);
                a[mi][2] = __float_as_uint(As[r * GLD + kk + 4]);
                a[mi][3] = __float_as_uint(As[(r + 8) * GLD + kk + 4]);
            }
#pragma unroll
            for (int ni = 0; ni < 4; ++ni) {
                const int c = cbase + 8 * ni + gid;
                unsigned b0 = __float_as_uint(Bs[c * GLD + kk]);
                unsigned b1 = __float_as_uint(Bs[c * GLD + kk + 4]);
#pragma unroll
                for (int mi = 0; mi < 2; ++mi)
                    mma_tf32(acc[mi][ni], a[mi][0], a[mi][1], a[mi][2], a[mi][3], b0, b1);
            }
        }
        __syncthreads();
    }

#pragma unroll
    for (int mi = 0; mi < 2; ++mi) {
#pragma unroll
        for (int ni = 0; ni < 4; ++ni) {
            const int r = row0 + rbase + 16 * mi + gid;
            const int c = col0 + cbase + 8 * ni + 2 * tig;
            float b0v = 0.f, b1v = 0.f;
            if (bias) { b0v = bias[c]; b1v = bias[c + 1]; }
            float2 o0 = make_float2(acc[mi][ni][0] + b0v, acc[mi][ni][1] + b1v);
            float2 o1 = make_float2(acc[mi][ni][2] + b0v, acc[mi][ni][3] + b1v);
            *(float2*)&C[(size_t)r * N + c] = o0;
            *(float2*)&C[(size_t)(r + 8) * N + c] = o1;
        }
    }
}

// ============================================================
// RoPE: table precompute (accurate dp range reduction) + apply
// ============================================================
__global__ void rope_table_kernel()
{
    int idx = blockIdx.x * blockDim.x + threadIdx.x;   // S_LEN*64
    int t = idx >> 6, d = idx & 63;
    float inv = powf(10000.0f, -(float)(2 * d) * (1.0f / 128.0f));
    float ang = (float)t * inv;
    double da = (double)ang;
    const double twopi = 6.283185307179586;
    da -= floor(da / twopi) * twopi;
    float r = (float)da;
    g_cos[idx] = cosf(r);
    g_sin[idx] = sinf(r);
}

__global__ void rope_apply_kernel(float* __restrict__ Q, float* __restrict__ K)
{
    const int s = blockIdx.x;
    const int total = (NH + NKV) * 64;
    for (int p = threadIdx.x; p < total; p += blockDim.x) {
        float* base;
        int d;
        if (p < NH * 64) {
            base = Q + (size_t)s * HID + (p >> 6) * HD;
            d = p & 63;
        } else {
            int p2 = p - NH * 64;
            base = K + (size_t)s * KVDIM + (p2 >> 6) * HD;
            d = p2 & 63;
        }
        float c  = g_cos[s * 64 + d];
        float sn = g_sin[s * 64 + d];
        float x0 = base[d], x1 = base[d + 64];
        base[d]      = x0 * c - x1 * sn;
        base[d + 64] = x1 * c + x0 * sn;
    }
}

// ============================================================
// Flash attention, tf32 mma, causal, GQA.
// 64x64 tiles. 8 warps: score tile warp grid 4(rows)x2(cols of 32),
// O tile warp grid 4(rows)x2(cols of 64). O accumulators stay in
// mma fragments across the KV loop; per-row rescale uses the
// documented m16n8 accumulator row mapping (gid, gid+8).
// ============================================================
#define QLD 132
#define VLD 136
#define PLD 68

__global__ __launch_bounds__(256, 1) void flash_tf32(
    const float* __restrict__ Q, const float* __restrict__ K,
    const float* __restrict__ V, float* __restrict__ Out)
{
    extern __shared__ float sm[];
    float* Qs    = sm;                  // 64*132
    float* Ks    = Qs + 64 * QLD;       // 64*132
    float* Vs    = Ks + 64 * QLD;       // 64*136 ([k][n])
    float* Ps    = Vs + 64 * VLD;       // 64*68
    float* row_m = Ps + 64 * PLD;       // 64
    float* row_l = row_m + 64;          // 64
    float* pmax  = row_l + 64;          // 2*64
    float* psum  = pmax + 128;          // 2*64

    const int h   = blockIdx.y;
    const int qt  = (int)gridDim.x - 1 - (int)blockIdx.x;
    const int kvh = h >> 2;
    const int tid = threadIdx.x;
    const int warp = tid >> 5, lane = tid & 31;
    const int gid = lane >> 2, tig = lane & 3;
    const int sr = (warp & 3) * 16;     // row base (both phases)
    const int sc = (warp >> 2) * 32;    // score col base
    const int oc = (warp >> 2) * 64;    // O col base
    const int wc = warp >> 2;

    if (tid < 64) { row_m[tid] = -1e30f; row_l[tid] = 0.0f; }

    // load Q tile (pre-scaled, tf32-rounded)
    {
        const int lr = tid >> 2, lc = (tid & 3) * 32;
        const float* qg = Q + (size_t)(qt * 64 + lr) * HID + h * HD + lc;
        float* qs = Qs + lr * QLD + lc;
        const float scale = 0.08838834764831843f;  // 1/sqrt(128)
#pragma unroll
        for (int i = 0; i < 8; ++i) {
            float4 v = *(const float4*)(qg + 4 * i);
            qs[4 * i + 0] = f2tf(v.x * scale);
            qs[4 * i + 1] = f2tf(v.y * scale);
            qs[4 * i + 2] = f2tf(v.z * scale);
            qs[4 * i + 3] = f2tf(v.w * scale);
        }
    }

    float oacc[8][4];
#pragma unroll
    for (int ni = 0; ni < 8; ++ni)
#pragma unroll
        for (int j = 0; j < 4; ++j) oacc[ni][j] = 0.0f;

    const int r0 = sr + gid, r1 = sr + gid + 8;

    for (int kt = 0; kt <= qt; ++kt) {
        // load K ([n][k]) and V ([k][n]) tiles
        {
            const int lr = tid >> 2, lc = (tid & 3) * 32;
            const float* kg = K + (size_t)(kt * 64 + lr) * KVDIM + kvh * HD + lc;
            const float* vg = V + (size_t)(kt * 64 + lr) * KVDIM + kvh * HD + lc;
            float* ks = Ks + lr * QLD + lc;
            float* vs = Vs + lr * VLD + lc;
#pragma unroll
            for (int i = 0; i < 8; ++i) {
                float4 kv = *(const float4*)(kg + 4 * i);
                float4 vv = *(const float4*)(vg + 4 * i);
                ks[4 * i + 0] = f2tf(kv.x); ks[4 * i + 1] = f2tf(kv.y);
                ks[4 * i + 2] = f2tf(kv.z); ks[4 * i + 3] = f2tf(kv.w);
                vs[4 * i + 0] = f2tf(vv.x); vs[4 * i + 1] = f2tf(vv.y);
                vs[4 * i + 2] = f2tf(vv.z); vs[4 * i + 3] = f2tf(vv.w);
            }
        }
        __syncthreads();   // (a)

        // ---- scores: S = Q K^T (tf32 mma) ----
        float sacc[4][4];
#pragma unroll
        for (int ni = 0; ni < 4; ++ni)
#pragma unroll
            for (int j = 0; j < 4; ++j) sacc[ni][j] = 0.0f;

#pragma unroll
        for (int ks = 0; ks < 16; ++ks) {
            const int kk = ks * 8 + tig;
            unsigned a0 = __float_as_uint(Qs[r0 * QLD + kk]);
            unsigned a1 = __float_as_uint(Qs[r1 * QLD + kk]);
            unsigned a2 = __float_as_uint(Qs[r0 * QLD + kk + 4]);
            unsigned a3 = __float_as_uint(Qs[r1 * QLD + kk + 4]);
#pragma unroll
            for (int ni = 0; ni < 4; ++ni) {
                const int c = sc + 8 * ni + gid;
                unsigned b0 = __float_as_uint(Ks[c * QLD + kk]);
                unsigned b1 = __float_as_uint(Ks[c * QLD + kk + 4]);
                mma_tf32(sacc[ni], a0, a1, a2, a3, b0, b1);
            }
        }

        // causal mask on diagonal tile
        if (kt == qt) {
#pragma unroll
            for (int ni = 0; ni < 4; ++ni) {
                const int c0 = sc + 8 * ni + 2 * tig;
                const int c1 = c0 + 1;
                if (c0 > r0) sacc[ni][0] = -1e30f;
                if (c1 > r0) sacc[ni][1] = -1e30f;
                if (c0 > r1) sacc[ni][2] = -1e30f;
                if (c1 > r1) sacc[ni][3] = -1e30f;
            }
        }

        // ---- partial row max (quad shuffle) ----
        float mx0 = -1e30f, mx1 = -1e30f;
#pragma unroll
        for (int ni = 0; ni < 4; ++ni) {
            mx0 = fmaxf(mx0, fmaxf(sacc[ni][0], sacc[ni][1]));
            mx1 = fmaxf(mx1, fmaxf(sacc[ni][2], sacc[ni][3]));
        }
        mx0 = fmaxf(mx0, __shfl_xor_sync(0xffffffffu, mx0, 1));
        mx0 = fmaxf(mx0, __shfl_xor_sync(0xffffffffu, mx0, 2));
        mx1 = fmaxf(mx1, __shfl_xor_sync(0xffffffffu, mx1, 1));
        mx1 = fmaxf(mx1, __shfl_xor_sync(0xffffffffu, mx1, 2));
        if (tig == 0) {
            pmax[wc * 64 + r0] = mx0;
            pmax[wc * 64 + r1] = mx1;
        }
        __syncthreads();   // (b)

        const float mo0 = row_m[r0], mo1 = row_m[r1];
        const float mn0 = fmaxf(mo0, fmaxf(pmax[r0], pmax[64 + r0]));
        const float mn1 = fmaxf(mo1, fmaxf(pmax[r1], pmax[64 + r1]));
        const float corr0 = __expf(mo0 - mn0);
        const float corr1 = __expf(mo1 - mn1);

        // ---- P = exp(S - m), store tf32 to smem, partial row sums ----
        float s0 = 0.0f, s1 = 0.0f;
#pragma unroll
        for (int ni = 0; ni < 4; ++ni) {
            const int c0 = sc + 8 * ni + 2 * tig;
            float p00 = __expf(sacc[ni][0] - mn0);
            float p01 = __expf(sacc[ni][1] - mn0);
            float p10 = __expf(sacc[ni][2] - mn1);
            float p11 = __expf(sacc[ni][3] - mn1);
            Ps[r0 * PLD + c0]     = f2tf(p00);
            Ps[r0 * PLD + c0 + 1] = f2tf(p01);
            Ps[r1 * PLD + c0]     = f2tf(p10);
            Ps[r1 * PLD + c0 + 1] = f2tf(p11);
            s0 += p00 + p01;
            s1 += p10 + p11;
        }
        s0 += __shfl_xor_sync(0xffffffffu, s0, 1);
        s0 += __shfl_xor_sync(0xffffffffu, s0, 2);
        s1 += __shfl_xor_sync(0xffffffffu, s1, 1);
        s1 += __shfl_xor_sync(0xffffffffu, s1, 2);
        if (tig == 0) {
            psum[wc * 64 + r0] = s0;
            psum[wc * 64 + r1] = s1;
        }
        __syncthreads();   // (c)

        if (wc == 0 && tig == 0) {
            row_m[r0] = mn0; row_m[r1] = mn1;
            row_l[r0] = row_l[r0] * corr0 + psum[r0] + psum[64 + r0];
            row_l[r1] = row_l[r1] * corr1 + psum[r1] + psum[64 + r1];
        }

        // ---- O = diag(corr) O + P V ----
#pragma unroll
        for (int ni = 0; ni < 8; ++ni) {
            oacc[ni][0] *= corr0; oacc[ni][1] *= corr0;
            oacc[ni][2] *= corr1; oacc[ni][3] *= corr1;
        }
#pragma unroll
        for (int ks = 0; ks < 8; ++ks) {
            const int kk = ks * 8 + tig;
            unsigned a0 = __float_as_uint(Ps[r0 * PLD + kk]);
            unsigned a1 = __float_as_uint(Ps[r1 * PLD + kk]);
            unsigned a2 = __float_as_uint(Ps[r0 * PLD + kk + 4]);
            unsigned a3 = __float_as_uint(Ps[r1 * PLD + kk + 4]);
#pragma unroll
            for (int ni = 0; ni < 8; ++ni) {
                const int c = oc + 8 * ni + gid;
                unsigned b0 = __float_as_uint(Vs[kk * VLD + c]);
                unsigned b1 = __float_as_uint(Vs[(kk + 4) * VLD + c]);
                mma_tf32(oacc[ni], a0, a1, a2, a3, b0, b1);
            }
        }
        __syncthreads();   // (d)
    }

    // ---- epilogue ----
    const float li0 = 1.0f / row_l[r0];
    const float li1 = 1.0f / row_l[r1];
#pragma unroll
    for (int ni = 0; ni < 8; ++ni) {
        const int row = qt * 64 + r0;
        const int col = h * HD + oc + 8 * ni + 2 * tig;
        float2 v0 = make_float2(oacc[ni][0] * li0, oacc[ni][1] * li0);
        float2 v1 = make_float2(oacc[ni][2] * li1, oacc[ni][3] * li1);
        *(float2*)&Out[(size_t)row * HID + col] = v0;
        *(float2*)&Out[(size_t)(row + 8) * HID + col] = v1;
    }
}

// ============================================================
// launch
// ============================================================
extern "C" void kernel_launch(void* const* d_in, const int* in_sizes, int n_in,
                              void* d_out, int out_size)
{
    const float* hidden = (const float*)d_in[0];
    // d_in[1] = attention_mask: exactly causal -> applied analytically
    const float* q_w = (const float*)d_in[2];
    const float* q_b = (const float*)d_in[3];
    const float* k_w = (const float*)d_in[4];
    const float* k_b = (const float*)d_in[5];
    const float* v_w = (const float*)d_in[6];
    const float* v_b = (const float*)d_in[7];
    const float* o_w = (const float*)d_in[8];
    float* out = (float*)d_out;

    float *Qp, *Kp, *Vp, *AOp;
    cudaGetSymbolAddress((void**)&Qp,  g_Q);
    cudaGetSymbolAddress((void**)&Kp,  g_K);
    cudaGetSymbolAddress((void**)&Vp,  g_V);
    cudaGetSymbolAddress((void**)&AOp, g_AO);

    // RoPE table (independent of projections)
    rope_table_kernel<<<(S_LEN * 64) / 256, 256>>>();

    // projections (tf32 tensor cores)
    gemm_tf32<<<dim3(HID / 64, S_LEN / 128), 256>>>(
        hidden, q_w, q_b, Qp, S_LEN, HID, HID);
    gemm_tf32<<<dim3(KVDIM / 64, S_LEN / 128), 256>>>(
        hidden, k_w, k_b, Kp, S_LEN, KVDIM, HID);
    gemm_tf32<<<dim3(KVDIM / 64, S_LEN / 128), 256>>>(
        hidden, v_w, v_b, Vp, S_LEN, KVDIM, HID);

    // RoPE apply
    rope_apply_kernel<<<S_LEN, 256>>>(Qp, Kp);

    // flash attention
    int smem = (2 * 64 * QLD + 64 * VLD + 64 * PLD + 64 * 2 + 256) * (int)sizeof(float);
    cudaFuncSetAttribute(flash_tf32,
                         cudaFuncAttributeMaxDynamicSharedMemorySize, smem);
    flash_tf32<<<dim3(64, NH), 256, smem>>>(Qp, Kp, Vp, AOp);

    // output projection
    gemm_tf32<<<dim3(HID / 64, S_LEN / 128), 256>>>(
        AOp, o_w, nullptr, out, S_LEN, HID, HID);
}

// round 5
// speedup vs baseline: 4.4939x; 1.4758x over previous
#include <cuda_runtime.h>
#include <cuda_bf16.h>
#include <cstdint>
#include <math.h>

#define S_LEN 4096
#define HID   2048
#define NH    16
#define NKV   4
#define HD    128
#define KVDIM (NKV * HD)   // 512

// -------- scratch (no allocs allowed) --------
__device__ float g_Q[S_LEN * HID];
__device__ float g_K[S_LEN * KVDIM];
__device__ float g_V[S_LEN * KVDIM];
__device__ float g_AO[S_LEN * HID];
__device__ float g_cos[S_LEN * 64];
__device__ float g_sin[S_LEN * 64];

// ---------- tf32 helpers ----------
__device__ __forceinline__ float f2tf(float x) {
    unsigned u;
    asm("cvt.rna.tf32.f32 %0, %1;" : "=r"(u) : "f"(x));
    return __uint_as_float(u);
}

__device__ __forceinline__ void mma_tf32(float* c,
    unsigned a0, unsigned a1, unsigned a2, unsigned a3,
    unsigned b0, unsigned b1)
{
    asm volatile(
        "mma.sync.aligned.m16n8k8.row.col.f32.tf32.tf32.f32 "
        "{%0,%1,%2,%3}, {%4,%5,%6,%7}, {%8,%9}, {%0,%1,%2,%3};\n"
        : "+f"(c[0]), "+f"(c[1]), "+f"(c[2]), "+f"(c[3])
        : "r"(a0), "r"(a1), "r"(a2), "r"(a3), "r"(b0), "r"(b1));
}

// ---------- cp.async helpers ----------
__device__ __forceinline__ void cp16(unsigned int s, const float* g) {
    asm volatile("cp.async.cg.shared.global [%0], [%1], 16;\n" :: "r"(s), "l"(g));
}
__device__ __forceinline__ void cp_commit() {
    asm volatile("cp.async.commit_group;\n");
}
template<int N> __device__ __forceinline__ void cp_wait() {
    asm volatile("cp.async.wait_group %0;\n" :: "n"(N));
}

// ============================================================
// tf32 tensor-core NT GEMM (unchanged from R2; proven)
// ============================================================
#define GLD 36
__global__ __launch_bounds__(256) void gemm_tf32(
    const float* __restrict__ A, const float* __restrict__ B,
    const float* __restrict__ bias, float* __restrict__ C,
    int M, int N, int K)
{
    __shared__ float As[128 * GLD];
    __shared__ float Bs[64 * GLD];

    const int tid  = threadIdx.x;
    const int warp = tid >> 5, lane = tid & 31;
    const int gid  = lane >> 2, tig = lane & 3;
    const int rbase = (warp & 3) * 32;
    const int cbase = (warp >> 2) * 32;
    const int row0 = blockIdx.y * 128;
    const int col0 = blockIdx.x * 64;

    float acc[2][4][4];
#pragma unroll
    for (int mi = 0; mi < 2; ++mi)
#pragma unroll
        for (int ni = 0; ni < 4; ++ni)
#pragma unroll
            for (int j = 0; j < 4; ++j) acc[mi][ni][j] = 0.0f;

    const int ar = tid >> 1, akc = (tid & 1) * 16;
    const int br = tid >> 2, bkc = (tid & 3) * 8;
    const float* Ag = A + (size_t)(row0 + ar) * K + akc;
    const float* Bg = B + (size_t)(col0 + br) * K + bkc;

    for (int k0 = 0; k0 < K; k0 += 32) {
#pragma unroll
        for (int i = 0; i < 4; ++i) {
            float4 v = *(const float4*)(Ag + k0 + 4 * i);
            float* d = &As[ar * GLD + akc + 4 * i];
            d[0] = f2tf(v.x); d[1] = f2tf(v.y);
            d[2] = f2tf(v.z); d[3] = f2tf(v.w);
        }
#pragma unroll
        for (int i = 0; i < 2; ++i) {
            float4 v = *(const float4*)(Bg + k0 + 4 * i);
            float* d = &Bs[br * GLD + bkc + 4 * i];
            d[0] = f2tf(v.x); d[1] = f2tf(v.y);
            d[2] = f2tf(v.z); d[3] = f2tf(v.w);
        }
        __syncthreads();
#pragma unroll
        for (int ks = 0; ks < 4; ++ks) {
            const int kk = ks * 8 + tig;
            unsigned a[2][4];
#pragma unroll
            for (int mi = 0; mi < 2; ++mi) {
                const int r = rbase + 16 * mi + gid;
                a[mi][0] = __float_as_uint(As[r * GLD + kk]);
                a[mi][1] = __float_as_uint(As[(r + 8) * GLD + kk]);
                a[mi][2] = __float_as_uint(As[r * GLD + kk + 4]);
                a[mi][3] = __float_as_uint(As[(r + 8) * GLD + kk + 4]);
            }
#pragma unroll
            for (int ni = 0; ni < 4; ++ni) {
                const int c = cbase + 8 * ni + gid;
                unsigned b0 = __float_as_uint(Bs[c * GLD + kk]);
                unsigned b1 = __float_as_uint(Bs[c * GLD + kk + 4]);
#pragma unroll
                for (int mi = 0; mi < 2; ++mi)
                    mma_tf32(acc[mi][ni], a[mi][0], a[mi][1], a[mi][2], a[mi][3], b0, b1);
            }
        }
        __syncthreads();
    }

#pragma unroll
    for (int mi = 0; mi < 2; ++mi) {
#pragma unroll
        for (int ni = 0; ni < 4; ++ni) {
            const int r = row0 + rbase + 16 * mi + gid;
            const int c = col0 + cbase + 8 * ni + 2 * tig;
            float b0v = 0.f, b1v = 0.f;
            if (bias) { b0v = bias[c]; b1v = bias[c + 1]; }
            float2 o0 = make_float2(acc[mi][ni][0] + b0v, acc[mi][ni][1] + b1v);
            float2 o1 = make_float2(acc[mi][ni][2] + b0v, acc[mi][ni][3] + b1v);
            *(float2*)&C[(size_t)r * N + c] = o0;
            *(float2*)&C[(size_t)(r + 8) * N + c] = o1;
        }
    }
}

// ============================================================
// RoPE table + apply. Apply also pre-scales Q by 1/sqrt(HD) and
// rounds Q/K/V to tf32 in place.
// ============================================================
__global__ void rope_table_kernel()
{
    int idx = blockIdx.x * blockDim.x + threadIdx.x;
    int t = idx >> 6, d = idx & 63;
    float inv = powf(10000.0f, -(float)(2 * d) * (1.0f / 128.0f));
    float ang = (float)t * inv;
    double da = (double)ang;
    const double twopi = 6.283185307179586;
    da -= floor(da / twopi) * twopi;
    float r = (float)da;
    g_cos[idx] = cosf(r);
    g_sin[idx] = sinf(r);
}

__global__ void rope_apply_kernel(float* __restrict__ Q, float* __restrict__ K,
                                  float* __restrict__ V)
{
    const int s = blockIdx.x;
    const float qscale = 0.08838834764831843f;  // 1/sqrt(128)
    const int total = (NH + NKV) * 64;
    for (int p = threadIdx.x; p < total; p += blockDim.x) {
        float c, sn;
        if (p < NH * 64) {
            float* base = Q + (size_t)s * HID + (p >> 6) * HD;
            int d = p & 63;
            c = g_cos[s * 64 + d]; sn = g_sin[s * 64 + d];
            float x0 = base[d], x1 = base[d + 64];
            base[d]      = f2tf((x0 * c - x1 * sn) * qscale);
            base[d + 64] = f2tf((x1 * c + x0 * sn) * qscale);
        } else {
            int p2 = p - NH * 64;
            float* base = K + (size_t)s * KVDIM + (p2 >> 6) * HD;
            int d = p2 & 63;
            c = g_cos[s * 64 + d]; sn = g_sin[s * 64 + d];
            float x0 = base[d], x1 = base[d + 64];
            base[d]      = f2tf(x0 * c - x1 * sn);
            base[d + 64] = f2tf(x1 * c + x0 * sn);
        }
    }
    float* vrow = V + (size_t)s * KVDIM;
    for (int p = threadIdx.x; p < KVDIM; p += blockDim.x)
        vrow[p] = f2tf(vrow[p]);
}

// ============================================================
// Flash attention v2: 128-row Q tiles, warp-owned rows (16/warp),
// cp.async K/V pipeline, tf32 mma, causal, GQA.
// ============================================================
#define QLD 132
#define KLD 132
#define VLD 136
#define PLD 68

__global__ __launch_bounds__(256, 1) void flash_tf32_v2(
    const float* __restrict__ Q, const float* __restrict__ K,
    const float* __restrict__ V, float* __restrict__ Out)
{
    extern __shared__ float sm[];
    float* Qs = sm;                       // 128*132
    float* Ks = Qs + 128 * QLD;           // 64*132
    float* Vs = Ks + 64 * KLD;            // 64*136  ([k][n])
    float* Ps = Vs + 64 * VLD;            // 8 warps * 16*68

    const int h   = blockIdx.y;
    const int qt  = (int)gridDim.x - 1 - (int)blockIdx.x;  // heavy first
    const int kvh = h >> 2;
    const int tid = threadIdx.x;
    const int warp = tid >> 5, lane = tid & 31;
    const int gid = lane >> 2, tig = lane & 3;
    const int wrow = warp * 16;
    float* Pw = Ps + warp * 16 * PLD;

    const unsigned int qs_b = (unsigned int)__cvta_generic_to_shared(Qs);
    const unsigned int ks_b = (unsigned int)__cvta_generic_to_shared(Ks);
    const unsigned int vs_b = (unsigned int)__cvta_generic_to_shared(Vs);

    // ---- prologue: Q + K0 (group A), V0 (group B) ----
#pragma unroll
    for (int i = 0; i < 16; ++i) {
        int idx = tid + 256 * i; int row = idx >> 5; int c4 = (idx & 31) << 2;
        cp16(qs_b + (unsigned int)(row * QLD + c4) * 4,
             Q + (size_t)(qt * 128 + row) * HID + h * HD + c4);
    }
#pragma unroll
    for (int i = 0; i < 8; ++i) {
        int idx = tid + 256 * i; int row = idx >> 5; int c4 = (idx & 31) << 2;
        cp16(ks_b + (unsigned int)(row * KLD + c4) * 4,
             K + (size_t)row * KVDIM + kvh * HD + c4);
    }
    cp_commit();
#pragma unroll
    for (int i = 0; i < 8; ++i) {
        int idx = tid + 256 * i; int row = idx >> 5; int c4 = (idx & 31) << 2;
        cp16(vs_b + (unsigned int)(row * VLD + c4) * 4,
             V + (size_t)row * KVDIM + kvh * HD + c4);
    }
    cp_commit();

    float oacc[16][4];
#pragma unroll
    for (int ni = 0; ni < 16; ++ni)
#pragma unroll
        for (int j = 0; j < 4; ++j) oacc[ni][j] = 0.0f;

    float m0 = -1e30f, m1 = -1e30f, l0 = 0.0f, l1 = 0.0f;
    const int ktmax = 2 * qt + 1;
    const int r0g = qt * 128 + wrow + gid;   // global row (accum rows 0/1)
    const int r1g = r0g + 8;                 //            (accum rows 2/3)

    for (int kt = 0; kt <= ktmax; ++kt) {
        cp_wait<1>();       // K(kt) landed
        __syncthreads();    // visible to all; prev Vs fully consumed

        const bool active = (kt * 64) <= (qt * 128 + wrow + 15);

        float sacc[8][4];
#pragma unroll
        for (int ni = 0; ni < 8; ++ni)
#pragma unroll
            for (int j = 0; j < 4; ++j) sacc[ni][j] = 0.0f;

        if (active) {
#pragma unroll
            for (int ks = 0; ks < 16; ++ks) {
                const int kk = ks * 8 + tig;
                unsigned a0 = __float_as_uint(Qs[(wrow + gid) * QLD + kk]);
                unsigned a1 = __float_as_uint(Qs[(wrow + gid + 8) * QLD + kk]);
                unsigned a2 = __float_as_uint(Qs[(wrow + gid) * QLD + kk + 4]);
                unsigned a3 = __float_as_uint(Qs[(wrow + gid + 8) * QLD + kk + 4]);
#pragma unroll
                for (int ni = 0; ni < 8; ++ni) {
                    const int c = 8 * ni + gid;
                    unsigned b0 = __float_as_uint(Ks[c * KLD + kk]);
                    unsigned b1 = __float_as_uint(Ks[c * KLD + kk + 4]);
                    mma_tf32(sacc[ni], a0, a1, a2, a3, b0, b1);
                }
            }
        }

        cp_wait<0>();       // V(kt) landed
        __syncthreads();    // visible; Ks consumed -> safe to refill
        if (kt < ktmax) {
#pragma unroll
            for (int i = 0; i < 8; ++i) {
                int idx = tid + 256 * i; int row = idx >> 5; int c4 = (idx & 31) << 2;
                cp16(ks_b + (unsigned int)(row * KLD + c4) * 4,
                     K + (size_t)((kt + 1) * 64 + row) * KVDIM + kvh * HD + c4);
            }
        }
        cp_commit();

        float corr0 = 1.0f, corr1 = 1.0f;
        if (active) {
            // causal mask (only if tile crosses the diagonal for this warp)
            if (kt * 64 + 63 > qt * 128 + wrow) {
                const int cb = kt * 64 + 2 * tig;
#pragma unroll
                for (int ni = 0; ni < 8; ++ni) {
                    const int c0 = cb + 8 * ni, c1 = c0 + 1;
                    if (c0 > r0g) sacc[ni][0] = -1e30f;
                    if (c1 > r0g) sacc[ni][1] = -1e30f;
                    if (c0 > r1g) sacc[ni][2] = -1e30f;
                    if (c1 > r1g) sacc[ni][3] = -1e30f;
                }
            }
            // row max (quad shuffle)
            float mx0 = -1e30f, mx1 = -1e30f;
#pragma unroll
            for (int ni = 0; ni < 8; ++ni) {
                mx0 = fmaxf(mx0, fmaxf(sacc[ni][0], sacc[ni][1]));
                mx1 = fmaxf(mx1, fmaxf(sacc[ni][2], sacc[ni][3]));
            }
            mx0 = fmaxf(mx0, __shfl_xor_sync(0xffffffffu, mx0, 1));
            mx0 = fmaxf(mx0, __shfl_xor_sync(0xffffffffu, mx0, 2));
            mx1 = fmaxf(mx1, __shfl_xor_sync(0xffffffffu, mx1, 1));
            mx1 = fmaxf(mx1, __shfl_xor_sync(0xffffffffu, mx1, 2));

            const float mn0 = fmaxf(m0, mx0);
            const float mn1 = fmaxf(m1, mx1);
            corr0 = __expf(m0 - mn0);
            corr1 = __expf(m1 - mn1);

            float s0 = 0.0f, s1 = 0.0f;
#pragma unroll
            for (int ni = 0; ni < 8; ++ni) {
                const int c0 = 8 * ni + 2 * tig;
                float p00 = __expf(sacc[ni][0] - mn0);
                float p01 = __expf(sacc[ni][1] - mn0);
                float p10 = __expf(sacc[ni][2] - mn1);
                float p11 = __expf(sacc[ni][3] - mn1);
                Pw[gid * PLD + c0]           = f2tf(p00);
                Pw[gid * PLD + c0 + 1]       = f2tf(p01);
                Pw[(gid + 8) * PLD + c0]     = f2tf(p10);
                Pw[(gid + 8) * PLD + c0 + 1] = f2tf(p11);
                s0 += p00 + p01;
                s1 += p10 + p11;
            }
            s0 += __shfl_xor_sync(0xffffffffu, s0, 1);
            s0 += __shfl_xor_sync(0xffffffffu, s0, 2);
            s1 += __shfl_xor_sync(0xffffffffu, s1, 1);
            s1 += __shfl_xor_sync(0xffffffffu, s1, 2);

            m0 = mn0; m1 = mn1;
            l0 = l0 * corr0 + s0;
            l1 = l1 * corr1 + s1;
        }
        __syncwarp();   // P (this warp's rows) visible to this warp

        if (active) {
#pragma unroll
            for (int ni = 0; ni < 16; ++ni) {
                oacc[ni][0] *= corr0; oacc[ni][1] *= corr0;
                oacc[ni][2] *= corr1; oacc[ni][3] *= corr1;
            }
#pragma unroll
            for (int ks = 0; ks < 8; ++ks) {
                const int kk = ks * 8 + tig;
                unsigned a0 = __float_as_uint(Pw[gid * PLD + kk]);
                unsigned a1 = __float_as_uint(Pw[(gid + 8) * PLD + kk]);
                unsigned a2 = __float_as_uint(Pw[gid * PLD + kk + 4]);
                unsigned a3 = __float_as_uint(Pw[(gid + 8) * PLD + kk + 4]);
#pragma unroll
                for (int ni = 0; ni < 16; ++ni) {
                    const int c = 8 * ni + gid;
                    unsigned b0 = __float_as_uint(Vs[kk * VLD + c]);
                    unsigned b1 = __float_as_uint(Vs[(kk + 4) * VLD + c]);
                    mma_tf32(oacc[ni], a0, a1, a2, a3, b0, b1);
                }
            }
        }
        __syncthreads();    // Vs consumed by all -> safe to refill
        if (kt < ktmax) {
#pragma unroll
            for (int i = 0; i < 8; ++i) {
                int idx = tid + 256 * i; int row = idx >> 5; int c4 = (idx & 31) << 2;
                cp16(vs_b + (unsigned int)(row * VLD + c4) * 4,
                     V + (size_t)((kt + 1) * 64 + row) * KVDIM + kvh * HD + c4);
            }
        }
        cp_commit();
    }

    // ---- epilogue ----
    const float li0 = 1.0f / l0;
    const float li1 = 1.0f / l1;
#pragma unroll
    for (int ni = 0; ni < 16; ++ni) {
        const int col = h * HD + 8 * ni + 2 * tig;
        float2 v0 = make_float2(oacc[ni][0] * li0, oacc[ni][1] * li0);
        float2 v1 = make_float2(oacc[ni][2] * li1, oacc[ni][3] * li1);
        *(float2*)&Out[(size_t)r0g * HID + col] = v0;
        *(float2*)&Out[(size_t)r1g * HID + col] = v1;
    }
}

// ============================================================
// launch
// ============================================================
extern "C" void kernel_launch(void* const* d_in, const int* in_sizes, int n_in,
                              void* d_out, int out_size)
{
    const float* hidden = (const float*)d_in[0];
    // d_in[1] = attention_mask: exactly causal -> applied analytically
    const float* q_w = (const float*)d_in[2];
    const float* q_b = (const float*)d_in[3];
    const float* k_w = (const float*)d_in[4];
    const float* k_b = (const float*)d_in[5];
    const float* v_w = (const float*)d_in[6];
    const float* v_b = (const float*)d_in[7];
    const float* o_w = (const float*)d_in[8];
    float* out = (float*)d_out;

    float *Qp, *Kp, *Vp, *AOp;
    cudaGetSymbolAddress((void**)&Qp,  g_Q);
    cudaGetSymbolAddress((void**)&Kp,  g_K);
    cudaGetSymbolAddress((void**)&Vp,  g_V);
    cudaGetSymbolAddress((void**)&AOp, g_AO);

    rope_table_kernel<<<(S_LEN * 64) / 256, 256>>>();

    gemm_tf32<<<dim3(HID / 64, S_LEN / 128), 256>>>(
        hidden, q_w, q_b, Qp, S_LEN, HID, HID);
    gemm_tf32<<<dim3(KVDIM / 64, S_LEN / 128), 256>>>(
        hidden, k_w, k_b, Kp, S_LEN, KVDIM, HID);
    gemm_tf32<<<dim3(KVDIM / 64, S_LEN / 128), 256>>>(
        hidden, v_w, v_b, Vp, S_LEN, KVDIM, HID);

    // RoPE + tf32 pre-round (Q scaled by 1/sqrt(HD))
    rope_apply_kernel<<<S_LEN, 256>>>(Qp, Kp, Vp);

    // flash attention v2
    int smem = (128 * QLD + 64 * KLD + 64 * VLD + 8 * 16 * PLD) * (int)sizeof(float);
    cudaFuncSetAttribute(flash_tf32_v2,
                         cudaFuncAttributeMaxDynamicSharedMemorySize, smem);
    flash_tf32_v2<<<dim3(S_LEN / 128, NH), 256, smem>>>(Qp, Kp, Vp, AOp);

    gemm_tf32<<<dim3(HID / 64, S_LEN / 128), 256>>>(
        AOp, o_w, nullptr, out, S_LEN, HID, HID);
}

// round 8
// speedup vs baseline: 5.4539x; 1.2136x over previous
#include <cuda_runtime.h>
#include <cuda_fp16.h>
#include <cstdint>
#include <math.h>

#define S_LEN 4096
#define HID   2048
#define NH    16
#define NKV   4
#define HD    128
#define KVDIM (NKV * HD)   // 512

// -------- scratch (no allocs allowed) --------
__device__ float  g_Q[S_LEN * HID];
__device__ float  g_K[S_LEN * KVDIM];
__device__ float  g_V[S_LEN * KVDIM];
__device__ float  g_AO[S_LEN * HID];
__device__ __half g_Qh[S_LEN * HID];
__device__ __half g_Kh[S_LEN * KVDIM];
__device__ __half g_Vh[S_LEN * KVDIM];
__device__ float  g_cos[S_LEN * 64];
__device__ float  g_sin[S_LEN * 64];

// ---------- tf32 helpers (GEMM, proven) ----------
__device__ __forceinline__ float f2tf(float x) {
    unsigned u;
    asm("cvt.rna.tf32.f32 %0, %1;" : "=r"(u) : "f"(x));
    return __uint_as_float(u);
}

__device__ __forceinline__ void mma_tf32(float* c,
    unsigned a0, unsigned a1, unsigned a2, unsigned a3,
    unsigned b0, unsigned b1)
{
    asm volatile(
        "mma.sync.aligned.m16n8k8.row.col.f32.tf32.tf32.f32 "
        "{%0,%1,%2,%3}, {%4,%5,%6,%7}, {%8,%9}, {%0,%1,%2,%3};\n"
        : "+f"(c[0]), "+f"(c[1]), "+f"(c[2]), "+f"(c[3])
        : "r"(a0), "r"(a1), "r"(a2), "r"(a3), "r"(b0), "r"(b1));
}

// ---------- fp16 helpers (flash) ----------
__device__ __forceinline__ void mma_f16(float* c,
    unsigned a0, unsigned a1, unsigned a2, unsigned a3,
    unsigned b0, unsigned b1)
{
    asm volatile(
        "mma.sync.aligned.m16n8k16.row.col.f32.f16.f16.f32 "
        "{%0,%1,%2,%3}, {%4,%5,%6,%7}, {%8,%9}, {%0,%1,%2,%3};\n"
        : "+f"(c[0]), "+f"(c[1]), "+f"(c[2]), "+f"(c[3])
        : "r"(a0), "r"(a1), "r"(a2), "r"(a3), "r"(b0), "r"(b1));
}

__device__ __forceinline__ void ldsm4(unsigned& d0, unsigned& d1,
                                      unsigned& d2, unsigned& d3, unsigned addr)
{
    asm volatile("ldmatrix.sync.aligned.m8n8.x4.shared.b16 {%0,%1,%2,%3}, [%4];\n"
                 : "=r"(d0), "=r"(d1), "=r"(d2), "=r"(d3) : "r"(addr));
}

__device__ __forceinline__ void ldsm4t(unsigned& d0, unsigned& d1,
                                       unsigned& d2, unsigned& d3, unsigned addr)
{
    asm volatile("ldmatrix.sync.aligned.m8n8.x4.trans.shared.b16 {%0,%1,%2,%3}, [%4];\n"
                 : "=r"(d0), "=r"(d1), "=r"(d2), "=r"(d3) : "r"(addr));
}

// ---------- cp.async ----------
__device__ __forceinline__ void cp16(unsigned s, const void* g) {
    asm volatile("cp.async.cg.shared.global [%0], [%1], 16;\n" :: "r"(s), "l"(g));
}
__device__ __forceinline__ void cp_commit() {
    asm volatile("cp.async.commit_group;\n");
}
template<int N> __device__ __forceinline__ void cp_wait() {
    asm volatile("cp.async.wait_group %0;\n" :: "n"(N));
}

// ============================================================
// tf32 tensor-core NT GEMM (verbatim from R5, proven)
// ============================================================
#define GLD 36
__global__ __launch_bounds__(256) void gemm_tf32(
    const float* __restrict__ A, const float* __restrict__ B,
    const float* __restrict__ bias, float* __restrict__ C,
    int M, int N, int K)
{
    __shared__ float As[128 * GLD];
    __shared__ float Bs[64 * GLD];

    const int tid  = threadIdx.x;
    const int warp = tid >> 5, lane = tid & 31;
    const int gid  = lane >> 2, tig = lane & 3;
    const int rbase = (warp & 3) * 32;
    const int cbase = (warp >> 2) * 32;
    const int row0 = blockIdx.y * 128;
    const int col0 = blockIdx.x * 64;

    float acc[2][4][4];
#pragma unroll
    for (int mi = 0; mi < 2; ++mi)
#pragma unroll
        for (int ni = 0; ni < 4; ++ni)
#pragma unroll
            for (int j = 0; j < 4; ++j) acc[mi][ni][j] = 0.0f;

    const int ar = tid >> 1, akc = (tid & 1) * 16;
    const int br = tid >> 2, bkc = (tid & 3) * 8;
    const float* Ag = A + (size_t)(row0 + ar) * K + akc;
    const float* Bg = B + (size_t)(col0 + br) * K + bkc;

    for (int k0 = 0; k0 < K; k0 += 32) {
#pragma unroll
        for (int i = 0; i < 4; ++i) {
            float4 v = *(const float4*)(Ag + k0 + 4 * i);
            float* d = &As[ar * GLD + akc + 4 * i];
            d[0] = f2tf(v.x); d[1] = f2tf(v.y);
            d[2] = f2tf(v.z); d[3] = f2tf(v.w);
        }
#pragma unroll
        for (int i = 0; i < 2; ++i) {
            float4 v = *(const float4*)(Bg + k0 + 4 * i);
            float* d = &Bs[br * GLD + bkc + 4 * i];
            d[0] = f2tf(v.x); d[1] = f2tf(v.y);
            d[2] = f2tf(v.z); d[3] = f2tf(v.w);
        }
        __syncthreads();
#pragma unroll
        for (int ks = 0; ks < 4; ++ks) {
            const int kk = ks * 8 + tig;
            unsigned a[2][4];
#pragma unroll
            for (int mi = 0; mi < 2; ++mi) {
                const int r = rbase + 16 * mi + gid;
                a[mi][0] = __float_as_uint(As[r * GLD + kk]);
                a[mi][1] = __float_as_uint(As[(r + 8) * GLD + kk]);
                a[mi][2] = __float_as_uint(As[r * GLD + kk + 4]);
                a[mi][3] = __float_as_uint(As[(r + 8) * GLD + kk + 4]);
            }
#pragma unroll
            for (int ni = 0; ni < 4; ++ni) {
                const int c = cbase + 8 * ni + gid;
                unsigned b0 = __float_as_uint(Bs[c * GLD + kk]);
                unsigned b1 = __float_as_uint(Bs[c * GLD + kk + 4]);
#pragma unroll
                for (int mi = 0; mi < 2; ++mi)
                    mma_tf32(acc[mi][ni], a[mi][0], a[mi][1], a[mi][2], a[mi][3], b0, b1);
            }
        }
        __syncthreads();
    }

#pragma unroll
    for (int mi = 0; mi < 2; ++mi) {
#pragma unroll
        for (int ni = 0; ni < 4; ++ni) {
            const int r = row0 + rbase + 16 * mi + gid;
            const int c = col0 + cbase + 8 * ni + 2 * tig;
            float b0v = 0.f, b1v = 0.f;
            if (bias) { b0v = bias[c]; b1v = bias[c + 1]; }
            float2 o0 = make_float2(acc[mi][ni][0] + b0v, acc[mi][ni][1] + b1v);
            float2 o1 = make_float2(acc[mi][ni][2] + b0v, acc[mi][ni][3] + b1v);
            *(float2*)&C[(size_t)r * N + c] = o0;
            *(float2*)&C[(size_t)(r + 8) * N + c] = o1;
        }
    }
}

// ============================================================
// RoPE table + apply (fp32 in, fp16 out; Q pre-scaled)
// ============================================================
__global__ void rope_table_kernel()
{
    int idx = blockIdx.x * blockDim.x + threadIdx.x;
    int t = idx >> 6, d = idx & 63;
    float inv = powf(10000.0f, -(float)(2 * d) * (1.0f / 128.0f));
    float ang = (float)t * inv;
    double da = (double)ang;
    const double twopi = 6.283185307179586;
    da -= floor(da / twopi) * twopi;
    float r = (float)da;
    g_cos[idx] = cosf(r);
    g_sin[idx] = sinf(r);
}

__global__ void rope_half_kernel(
    const float* __restrict__ Q, const float* __restrict__ K,
    const float* __restrict__ V,
    __half* __restrict__ Qh, __half* __restrict__ Kh, __half* __restrict__ Vh)
{
    const int s = blockIdx.x;
    const float qscale = 0.08838834764831843f;  // 1/sqrt(128)
    const int total = (NH + NKV) * 64;
    for (int p = threadIdx.x; p < total; p += blockDim.x) {
        if (p < NH * 64) {
            const float* base = Q + (size_t)s * HID + (p >> 6) * HD;
            __half* ob = Qh + (size_t)s * HID + (p >> 6) * HD;
            int d = p & 63;
            float c = g_cos[s * 64 + d], sn = g_sin[s * 64 + d];
            float x0 = base[d], x1 = base[d + 64];
            ob[d]      = __float2half((x0 * c - x1 * sn) * qscale);
            ob[d + 64] = __float2half((x1 * c + x0 * sn) * qscale);
        } else {
            int p2 = p - NH * 64;
            const float* base = K + (size_t)s * KVDIM + (p2 >> 6) * HD;
            __half* ob = Kh + (size_t)s * KVDIM + (p2 >> 6) * HD;
            int d = p2 & 63;
            float c = g_cos[s * 64 + d], sn = g_sin[s * 64 + d];
            float x0 = base[d], x1 = base[d + 64];
            ob[d]      = __float2half(x0 * c - x1 * sn);
            ob[d + 64] = __float2half(x1 * c + x0 * sn);
        }
    }
    const float* vrow = V + (size_t)s * KVDIM;
    __half* vo = Vh + (size_t)s * KVDIM;
    for (int p = threadIdx.x; p < KVDIM; p += blockDim.x)
        vo[p] = __float2half(vrow[p]);
}

// ============================================================
// Flash attention fp16: 128-row Q tiles, warp-owned rows,
// cp.async K/V pipeline (R5 skeleton), HMMA + ldmatrix, causal, GQA.
// Output: float AO.
// ============================================================
#define QLD 136   // halves (272B)
#define PLD 72    // halves (144B)

__global__ __launch_bounds__(256, 1) void flash_f16(
    const __half* __restrict__ Q, const __half* __restrict__ K,
    const __half* __restrict__ V, float* __restrict__ Out)
{
    extern __shared__ __half sm[];
    __half* Qs = sm;                      // 128*136
    __half* Ks = Qs + 128 * QLD;          // 64*136  [n][k]
    __half* Vs = Ks + 64 * QLD;           // 64*136  [k][n]
    __half* Ps = Vs + 64 * QLD;           // 8 warps * 16*72

    const int h   = blockIdx.y;
    const int qt  = (int)gridDim.x - 1 - (int)blockIdx.x;  // heavy first
    const int kvh = h >> 2;
    const int tid = threadIdx.x;
    const int warp = tid >> 5, lane = tid & 31;
    const int gid = lane >> 2, tig = lane & 3;
    const int wrow = warp * 16;
    __half* Pw = Ps + warp * 16 * PLD;

    const int a_r = (lane & 7) + 8 * ((lane >> 3) & 1);
    const int a_c = 8 * (lane >> 4);
    const int b_r = (lane & 7) + 8 * (lane >> 4);
    const int b_c = 8 * ((lane >> 3) & 1);

    const unsigned qs_b = (unsigned)__cvta_generic_to_shared(Qs);
    const unsigned ks_b = (unsigned)__cvta_generic_to_shared(Ks);
    const unsigned vs_b = (unsigned)__cvta_generic_to_shared(Vs);
    const unsigned pw_b = (unsigned)__cvta_generic_to_shared(Pw);

    // ---- prologue: Q + K0 (group A), V0 (group B) ----
#pragma unroll
    for (int i = 0; i < 8; ++i) {
        int idx = tid + 256 * i; int row = idx >> 4; int c8 = (idx & 15) * 8;
        cp16(qs_b + (unsigned)(row * QLD + c8) * 2,
             Q + (size_t)(qt * 128 + row) * HID + h * HD + c8);
    }
#pragma unroll
    for (int i = 0; i < 4; ++i) {
        int idx = tid + 256 * i; int row = idx >> 4; int c8 = (idx & 15) * 8;
        cp16(ks_b + (unsigned)(row * QLD + c8) * 2,
             K + (size_t)row * KVDIM + kvh * HD + c8);
    }
    cp_commit();
#pragma unroll
    for (int i = 0; i < 4; ++i) {
        int idx = tid + 256 * i; int row = idx >> 4; int c8 = (idx & 15) * 8;
        cp16(vs_b + (unsigned)(row * QLD + c8) * 2,
             V + (size_t)row * KVDIM + kvh * HD + c8);
    }
    cp_commit();

    float oacc[16][4];
#pragma unroll
    for (int ni = 0; ni < 16; ++ni)
#pragma unroll
        for (int j = 0; j < 4; ++j) oacc[ni][j] = 0.0f;

    float m0 = -1e30f, m1 = -1e30f, l0 = 0.0f, l1 = 0.0f;
    const int ktmax = 2 * qt + 1;
    const int r0g = qt * 128 + wrow + gid;
    const int r1g = r0g + 8;

    for (int kt = 0; kt <= ktmax; ++kt) {
        cp_wait<1>();       // K(kt) (and Q on first iter) landed
        __syncthreads();

        const bool active = (kt * 64) <= (qt * 128 + wrow + 15);

        float sacc[8][4];
#pragma unroll
        for (int ni = 0; ni < 8; ++ni)
#pragma unroll
            for (int j = 0; j < 4; ++j) sacc[ni][j] = 0.0f;

        if (active) {
#pragma unroll
            for (int kb = 0; kb < 8; ++kb) {
                unsigned a0, a1, a2, a3;
                ldsm4(a0, a1, a2, a3,
                      qs_b + (unsigned)((wrow + a_r) * QLD + kb * 16 + a_c) * 2);
#pragma unroll
                for (int np = 0; np < 4; ++np) {
                    unsigned b0, b1, b2, b3;
                    ldsm4(b0, b1, b2, b3,
                          ks_b + (unsigned)((np * 16 + b_r) * QLD + kb * 16 + b_c) * 2);
                    mma_f16(sacc[2 * np],     a0, a1, a2, a3, b0, b1);
                    mma_f16(sacc[2 * np + 1], a0, a1, a2, a3, b2, b3);
                }
            }
        }

        cp_wait<0>();       // V(kt) landed
        __syncthreads();    // Ks consumed -> refill
        if (kt < ktmax) {
#pragma unroll
            for (int i = 0; i < 4; ++i) {
                int idx = tid + 256 * i; int row = idx >> 4; int c8 = (idx & 15) * 8;
                cp16(ks_b + (unsigned)(row * QLD + c8) * 2,
                     K + (size_t)((kt + 1) * 64 + row) * KVDIM + kvh * HD + c8);
            }
        }
        cp_commit();

        float corr0 = 1.0f, corr1 = 1.0f;
        if (active) {
            if (kt * 64 + 63 > qt * 128 + wrow) {
                const int cb = kt * 64 + 2 * tig;
#pragma unroll
                for (int ni = 0; ni < 8; ++ni) {
                    const int c0 = cb + 8 * ni, c1 = c0 + 1;
                    if (c0 > r0g) sacc[ni][0] = -1e30f;
                    if (c1 > r0g) sacc[ni][1] = -1e30f;
                    if (c0 > r1g) sacc[ni][2] = -1e30f;
                    if (c1 > r1g) sacc[ni][3] = -1e30f;
                }
            }
            float mx0 = -1e30f, mx1 = -1e30f;
#pragma unroll
            for (int ni = 0; ni < 8; ++ni) {
                mx0 = fmaxf(mx0, fmaxf(sacc[ni][0], sacc[ni][1]));
                mx1 = fmaxf(mx1, fmaxf(sacc[ni][2], sacc[ni][3]));
            }
            mx0 = fmaxf(mx0, __shfl_xor_sync(0xffffffffu, mx0, 1));
            mx0 = fmaxf(mx0, __shfl_xor_sync(0xffffffffu, mx0, 2));
            mx1 = fmaxf(mx1, __shfl_xor_sync(0xffffffffu, mx1, 1));
            mx1 = fmaxf(mx1, __shfl_xor_sync(0xffffffffu, mx1, 2));

            const float mn0 = fmaxf(m0, mx0);
            const float mn1 = fmaxf(m1, mx1);
            corr0 = __expf(m0 - mn0);
            corr1 = __expf(m1 - mn1);

            float s0 = 0.0f, s1 = 0.0f;
#pragma unroll
            for (int ni = 0; ni < 8; ++ni) {
                const int c0 = 8 * ni + 2 * tig;
                float p00 = __expf(sacc[ni][0] - mn0);
                float p01 = __expf(sacc[ni][1] - mn0);
                float p10 = __expf(sacc[ni][2] - mn1);
                float p11 = __expf(sacc[ni][3] - mn1);
                *(__half2*)&Pw[gid * PLD + c0]       = __floats2half2_rn(p00, p01);
                *(__half2*)&Pw[(gid + 8) * PLD + c0] = __floats2half2_rn(p10, p11);
                s0 += p00 + p01;
                s1 += p10 + p11;
            }
            s0 += __shfl_xor_sync(0xffffffffu, s0, 1);
            s0 += __shfl_xor_sync(0xffffffffu, s0, 2);
            s1 += __shfl_xor_sync(0xffffffffu, s1, 1);
            s1 += __shfl_xor_sync(0xffffffffu, s1, 2);

            m0 = mn0; m1 = mn1;
            l0 = l0 * corr0 + s0;
            l1 = l1 * corr1 + s1;
        }
        __syncwarp();

        if (active) {
#pragma unroll
            for (int ni = 0; ni < 16; ++ni) {
                oacc[ni][0] *= corr0; oacc[ni][1] *= corr0;
                oacc[ni][2] *= corr1; oacc[ni][3] *= corr1;
            }
#pragma unroll
            for (int kb = 0; kb < 4; ++kb) {
                unsigned a0, a1, a2, a3;
                ldsm4(a0, a1, a2, a3,
                      pw_b + (unsigned)(a_r * PLD + kb * 16 + a_c) * 2);
#pragma unroll
                for (int np = 0; np < 8; ++np) {
                    unsigned v0, v1, v2, v3;
                    ldsm4t(v0, v1, v2, v3,
                           vs_b + (unsigned)((kb * 16 + a_r) * QLD + np * 16 + a_c) * 2);
                    mma_f16(oacc[2 * np],     a0, a1, a2, a3, v0, v1);
                    mma_f16(oacc[2 * np + 1], a0, a1, a2, a3, v2, v3);
                }
            }
        }
        __syncthreads();    // Vs consumed -> refill
        if (kt < ktmax) {
#pragma unroll
            for (int i = 0; i < 4; ++i) {
                int idx = tid + 256 * i; int row = idx >> 4; int c8 = (idx & 15) * 8;
                cp16(vs_b + (unsigned)(row * QLD + c8) * 2,
                     V + (size_t)((kt + 1) * 64 + row) * KVDIM + kvh * HD + c8);
            }
        }
        cp_commit();
    }

    // ---- epilogue (float AO) ----
    const float li0 = 1.0f / l0;
    const float li1 = 1.0f / l1;
#pragma unroll
    for (int ni = 0; ni < 16; ++ni) {
        const int col = h * HD + 8 * ni + 2 * tig;
        *(float2*)&Out[(size_t)r0g * HID + col] =
            make_float2(oacc[ni][0] * li0, oacc[ni][1] * li0);
        *(float2*)&Out[(size_t)r1g * HID + col] =
            make_float2(oacc[ni][2] * li1, oacc[ni][3] * li1);
    }
}

// ============================================================
// launch
// ============================================================
extern "C" void kernel_launch(void* const* d_in, const int* in_sizes, int n_in,
                              void* d_out, int out_size)
{
    const float* hidden = (const float*)d_in[0];
    // d_in[1] = attention_mask: exactly causal -> applied analytically
    const float* q_w = (const float*)d_in[2];
    const float* q_b = (const float*)d_in[3];
    const float* k_w = (const float*)d_in[4];
    const float* k_b = (const float*)d_in[5];
    const float* v_w = (const float*)d_in[6];
    const float* v_b = (const float*)d_in[7];
    const float* o_w = (const float*)d_in[8];
    float* out = (float*)d_out;

    float *Qp, *Kp, *Vp, *AOp;
    __half *Qh, *Kh, *Vh;
    cudaGetSymbolAddress((void**)&Qp,  g_Q);
    cudaGetSymbolAddress((void**)&Kp,  g_K);
    cudaGetSymbolAddress((void**)&Vp,  g_V);
    cudaGetSymbolAddress((void**)&AOp, g_AO);
    cudaGetSymbolAddress((void**)&Qh,  g_Qh);
    cudaGetSymbolAddress((void**)&Kh,  g_Kh);
    cudaGetSymbolAddress((void**)&Vh,  g_Vh);

    rope_table_kernel<<<(S_LEN * 64) / 256, 256>>>();

    // projections (tf32, proven)
    gemm_tf32<<<dim3(HID / 64, S_LEN / 128), 256>>>(
        hidden, q_w, q_b, Qp, S_LEN, HID, HID);
    gemm_tf32<<<dim3(KVDIM / 64, S_LEN / 128), 256>>>(
        hidden, k_w, k_b, Kp, S_LEN, KVDIM, HID);
    gemm_tf32<<<dim3(KVDIM / 64, S_LEN / 128), 256>>>(
        hidden, v_w, v_b, Vp, S_LEN, KVDIM, HID);

    // RoPE + fp16 conversion (Q scaled by 1/sqrt(HD))
    rope_half_kernel<<<S_LEN, 256>>>(Qp, Kp, Vp, Qh, Kh, Vh);

    // flash attention (fp16 in, float out)
    int smem = (128 * QLD + 64 * QLD + 64 * QLD + 8 * 16 * PLD) * (int)sizeof(__half);
    cudaFuncSetAttribute(flash_f16,
                         cudaFuncAttributeMaxDynamicSharedMemorySize, smem);
    flash_f16<<<dim3(S_LEN / 128, NH), 256, smem>>>(Qh, Kh, Vh, AOp);

    // output projection (tf32, proven)
    gemm_tf32<<<dim3(HID / 64, S_LEN / 128), 256>>>(
        AOp, o_w, nullptr, out, S_LEN, HID, HID);
}

// round 9
// speedup vs baseline: 7.5442x; 1.3833x over previous
#include <cuda_runtime.h>
#include <cuda_fp16.h>
#include <cstdint>
#include <math.h>

#define S_LEN 4096
#define HID   2048
#define NH    16
#define NKV   4
#define HD    128
#define KVDIM (NKV * HD)   // 512

// -------- scratch (no allocs allowed) --------
__device__ float  g_Q[S_LEN * HID];
__device__ float  g_K[S_LEN * KVDIM];
__device__ float  g_V[S_LEN * KVDIM];
__device__ __half g_Xh[S_LEN * HID];
__device__ __half g_Wq[HID * HID];
__device__ __half g_Wk[KVDIM * HID];
__device__ __half g_Wv[KVDIM * HID];
__device__ __half g_Wo[HID * HID];
__device__ __half g_Qh[S_LEN * HID];
__device__ __half g_Kh[S_LEN * KVDIM];
__device__ __half g_Vh[S_LEN * KVDIM];
__device__ __half g_AOh[S_LEN * HID];
__device__ float  g_cos[S_LEN * 64];
__device__ float  g_sin[S_LEN * 64];

// ---------- fp16 mma / ldmatrix ----------
__device__ __forceinline__ void mma_f16(float* c,
    unsigned a0, unsigned a1, unsigned a2, unsigned a3,
    unsigned b0, unsigned b1)
{
    asm volatile(
        "mma.sync.aligned.m16n8k16.row.col.f32.f16.f16.f32 "
        "{%0,%1,%2,%3}, {%4,%5,%6,%7}, {%8,%9}, {%0,%1,%2,%3};\n"
        : "+f"(c[0]), "+f"(c[1]), "+f"(c[2]), "+f"(c[3])
        : "r"(a0), "r"(a1), "r"(a2), "r"(a3), "r"(b0), "r"(b1));
}

__device__ __forceinline__ void ldsm4(unsigned& d0, unsigned& d1,
                                      unsigned& d2, unsigned& d3, unsigned addr)
{
    asm volatile("ldmatrix.sync.aligned.m8n8.x4.shared.b16 {%0,%1,%2,%3}, [%4];\n"
                 : "=r"(d0), "=r"(d1), "=r"(d2), "=r"(d3) : "r"(addr));
}

__device__ __forceinline__ void ldsm4t(unsigned& d0, unsigned& d1,
                                       unsigned& d2, unsigned& d3, unsigned addr)
{
    asm volatile("ldmatrix.sync.aligned.m8n8.x4.trans.shared.b16 {%0,%1,%2,%3}, [%4];\n"
                 : "=r"(d0), "=r"(d1), "=r"(d2), "=r"(d3) : "r"(addr));
}

// ---------- cp.async (flash only; proven) ----------
__device__ __forceinline__ void cp16(unsigned s, const void* g) {
    asm volatile("cp.async.cg.shared.global [%0], [%1], 16;\n" :: "r"(s), "l"(g));
}
__device__ __forceinline__ void cp_commit() {
    asm volatile("cp.async.commit_group;\n");
}
template<int N> __device__ __forceinline__ void cp_wait() {
    asm volatile("cp.async.wait_group %0;\n" :: "n"(N));
}

// ---------- epilogue store ----------
__device__ __forceinline__ void store2(float* p, float x, float y) {
    *(float2*)p = make_float2(x, y);
}
__device__ __forceinline__ void store2(__half* p, float x, float y) {
    *(__half2*)p = __floats2half2_rn(x, y);
}

// ============================================================
// fp32 -> fp16 conversion (vectorized)
// ============================================================
__global__ void f32_to_f16(const float* __restrict__ src, __half* __restrict__ dst, int n)
{
    int i = (blockIdx.x * blockDim.x + threadIdx.x) * 4;
    if (i < n) {
        float4 v = *(const float4*)(src + i);
        *(__half2*)(dst + i)     = __floats2half2_rn(v.x, v.y);
        *(__half2*)(dst + i + 2) = __floats2half2_rn(v.z, v.w);
    }
}

// ============================================================
// fp16 NT GEMM: C[m,n] = sum_k A[m,k]*B[n,k] + bias[n]
// 128x64 tile, BK=32, 256 threads. SINGLE-buffered (R5 skeleton:
// plain LDG->STS + 2 barriers/step), ldmatrix + HMMA m16n8k16.
// ============================================================
#define ALD 40   // half stride (80B, 16B-multiple; 80=16*5 -> ldsm conflict-free)
template<typename OutT>
__global__ __launch_bounds__(256) void gemm_f16(
    const __half* __restrict__ A, const __half* __restrict__ B,
    const float* __restrict__ bias, OutT* __restrict__ C,
    int M, int N, int K)
{
    __shared__ __half As[128 * ALD];
    __shared__ __half Bs[64 * ALD];

    const int tid  = threadIdx.x;
    const int warp = tid >> 5, lane = tid & 31;
    const int gid  = lane >> 2, tig = lane & 3;
    const int rbase = (warp & 3) * 32;
    const int cbase = (warp >> 2) * 32;
    const int row0 = blockIdx.y * 128;
    const int col0 = blockIdx.x * 64;

    // ldmatrix per-lane maps (validated in R7 flash)
    const int a_r = (lane & 7) + 8 * ((lane >> 3) & 1);
    const int a_c = 8 * (lane >> 4);
    const int b_r = (lane & 7) + 8 * (lane >> 4);
    const int b_c = 8 * ((lane >> 3) & 1);

    const unsigned as_b = (unsigned)__cvta_generic_to_shared(As);
    const unsigned bs_b = (unsigned)__cvta_generic_to_shared(Bs);

    const int ar  = tid >> 1;            // A row 0..127
    const int akc = (tid & 1) * 16;      // half offset 0/16
    const int br  = tid >> 2;            // B row 0..63
    const int bkc = (tid & 3) * 8;       // half offset 0/8/16/24

    const __half* Ag = A + (size_t)(row0 + ar) * K + akc;
    const __half* Bg = B + (size_t)(col0 + br) * K + bkc;

    float acc[2][4][4];
#pragma unroll
    for (int mi = 0; mi < 2; ++mi)
#pragma unroll
        for (int n8 = 0; n8 < 4; ++n8)
#pragma unroll
            for (int j = 0; j < 4; ++j) acc[mi][n8][j] = 0.0f;

    for (int k0 = 0; k0 < K; k0 += 32) {
        uint4 va0 = *(const uint4*)(Ag + k0);
        uint4 va1 = *(const uint4*)(Ag + k0 + 8);
        uint4 vb  = *(const uint4*)(Bg + k0);
        *(uint4*)&As[ar * ALD + akc]     = va0;
        *(uint4*)&As[ar * ALD + akc + 8] = va1;
        *(uint4*)&Bs[br * ALD + bkc]     = vb;
        __syncthreads();

#pragma unroll
        for (int kb = 0; kb < 2; ++kb) {
            unsigned a[2][4];
#pragma unroll
            for (int mi = 0; mi < 2; ++mi) {
                ldsm4(a[mi][0], a[mi][1], a[mi][2], a[mi][3],
                      as_b + (unsigned)((rbase + 16 * mi + a_r) * ALD + kb * 16 + a_c) * 2);
            }
#pragma unroll
            for (int np = 0; np < 2; ++np) {
                unsigned b0, b1, b2, b3;
                ldsm4(b0, b1, b2, b3,
                      bs_b + (unsigned)((cbase + 16 * np + b_r) * ALD + kb * 16 + b_c) * 2);
#pragma unroll
                for (int mi = 0; mi < 2; ++mi) {
                    mma_f16(acc[mi][2 * np],     a[mi][0], a[mi][1], a[mi][2], a[mi][3], b0, b1);
                    mma_f16(acc[mi][2 * np + 1], a[mi][0], a[mi][1], a[mi][2], a[mi][3], b2, b3);
                }
            }
        }
        __syncthreads();
    }

#pragma unroll
    for (int mi = 0; mi < 2; ++mi) {
#pragma unroll
        for (int n8 = 0; n8 < 4; ++n8) {
            const int r = row0 + rbase + 16 * mi + gid;
            const int c = col0 + cbase + 8 * n8 + 2 * tig;
            float b0v = 0.f, b1v = 0.f;
            if (bias) { b0v = bias[c]; b1v = bias[c + 1]; }
            store2(&C[(size_t)r * N + c], acc[mi][n8][0] + b0v, acc[mi][n8][1] + b1v);
            store2(&C[(size_t)(r + 8) * N + c], acc[mi][n8][2] + b0v, acc[mi][n8][3] + b1v);
        }
    }
}

// ============================================================
// RoPE table + apply (fp32 in, fp16 out; Q pre-scaled)
// ============================================================
__global__ void rope_table_kernel()
{
    int idx = blockIdx.x * blockDim.x + threadIdx.x;
    int t = idx >> 6, d = idx & 63;
    float inv = powf(10000.0f, -(float)(2 * d) * (1.0f / 128.0f));
    float ang = (float)t * inv;
    double da = (double)ang;
    const double twopi = 6.283185307179586;
    da -= floor(da / twopi) * twopi;
    float r = (float)da;
    g_cos[idx] = cosf(r);
    g_sin[idx] = sinf(r);
}

__global__ void rope_half_kernel(
    const float* __restrict__ Q, const float* __restrict__ K,
    const float* __restrict__ V,
    __half* __restrict__ Qh, __half* __restrict__ Kh, __half* __restrict__ Vh)
{
    const int s = blockIdx.x;
    const float qscale = 0.08838834764831843f;  // 1/sqrt(128)
    const int total = (NH + NKV) * 64;
    for (int p = threadIdx.x; p < total; p += blockDim.x) {
        if (p < NH * 64) {
            const float* base = Q + (size_t)s * HID + (p >> 6) * HD;
            __half* ob = Qh + (size_t)s * HID + (p >> 6) * HD;
            int d = p & 63;
            float c = g_cos[s * 64 + d], sn = g_sin[s * 64 + d];
            float x0 = base[d], x1 = base[d + 64];
            ob[d]      = __float2half((x0 * c - x1 * sn) * qscale);
            ob[d + 64] = __float2half((x1 * c + x0 * sn) * qscale);
        } else {
            int p2 = p - NH * 64;
            const float* base = K + (size_t)s * KVDIM + (p2 >> 6) * HD;
            __half* ob = Kh + (size_t)s * KVDIM + (p2 >> 6) * HD;
            int d = p2 & 63;
            float c = g_cos[s * 64 + d], sn = g_sin[s * 64 + d];
            float x0 = base[d], x1 = base[d + 64];
            ob[d]      = __float2half(x0 * c - x1 * sn);
            ob[d + 64] = __float2half(x1 * c + x0 * sn);
        }
    }
    const float* vrow = V + (size_t)s * KVDIM;
    __half* vo = Vh + (size_t)s * KVDIM;
    for (int p = threadIdx.x; p < KVDIM; p += blockDim.x)
        vo[p] = __float2half(vrow[p]);
}

// ============================================================
// Flash attention fp16 (verbatim R7, except: half AO output)
// ============================================================
#define QLD 136   // halves (272B)
#define PLD 72    // halves (144B)

__global__ __launch_bounds__(256, 1) void flash_f16(
    const __half* __restrict__ Q, const __half* __restrict__ K,
    const __half* __restrict__ V, __half* __restrict__ Out)
{
    extern __shared__ __half sm[];
    __half* Qs = sm;                      // 128*136
    __half* Ks = Qs + 128 * QLD;          // 64*136  [n][k]
    __half* Vs = Ks + 64 * QLD;           // 64*136  [k][n]
    __half* Ps = Vs + 64 * QLD;           // 8 warps * 16*72

    const int h   = blockIdx.y;
    const int qt  = (int)gridDim.x - 1 - (int)blockIdx.x;  // heavy first
    const int kvh = h >> 2;
    const int tid = threadIdx.x;
    const int warp = tid >> 5, lane = tid & 31;
    const int gid = lane >> 2, tig = lane & 3;
    const int wrow = warp * 16;
    __half* Pw = Ps + warp * 16 * PLD;

    const int a_r = (lane & 7) + 8 * ((lane >> 3) & 1);
    const int a_c = 8 * (lane >> 4);
    const int b_r = (lane & 7) + 8 * (lane >> 4);
    const int b_c = 8 * ((lane >> 3) & 1);

    const unsigned qs_b = (unsigned)__cvta_generic_to_shared(Qs);
    const unsigned ks_b = (unsigned)__cvta_generic_to_shared(Ks);
    const unsigned vs_b = (unsigned)__cvta_generic_to_shared(Vs);
    const unsigned pw_b = (unsigned)__cvta_generic_to_shared(Pw);

    // ---- prologue: Q + K0 (group A), V0 (group B) ----
#pragma unroll
    for (int i = 0; i < 8; ++i) {
        int idx = tid + 256 * i; int row = idx >> 4; int c8 = (idx & 15) * 8;
        cp16(qs_b + (unsigned)(row * QLD + c8) * 2,
             Q + (size_t)(qt * 128 + row) * HID + h * HD + c8);
    }
#pragma unroll
    for (int i = 0; i < 4; ++i) {
        int idx = tid + 256 * i; int row = idx >> 4; int c8 = (idx & 15) * 8;
        cp16(ks_b + (unsigned)(row * QLD + c8) * 2,
             K + (size_t)row * KVDIM + kvh * HD + c8);
    }
    cp_commit();
#pragma unroll
    for (int i = 0; i < 4; ++i) {
        int idx = tid + 256 * i; int row = idx >> 4; int c8 = (idx & 15) * 8;
        cp16(vs_b + (unsigned)(row * QLD + c8) * 2,
             V + (size_t)row * KVDIM + kvh * HD + c8);
    }
    cp_commit();

    float oacc[16][4];
#pragma unroll
    for (int ni = 0; ni < 16; ++ni)
#pragma unroll
        for (int j = 0; j < 4; ++j) oacc[ni][j] = 0.0f;

    float m0 = -1e30f, m1 = -1e30f, l0 = 0.0f, l1 = 0.0f;
    const int ktmax = 2 * qt + 1;
    const int r0g = qt * 128 + wrow + gid;
    const int r1g = r0g + 8;

    for (int kt = 0; kt <= ktmax; ++kt) {
        cp_wait<1>();       // K(kt) (and Q on first iter) landed
        __syncthreads();

        const bool active = (kt * 64) <= (qt * 128 + wrow + 15);

        float sacc[8][4];
#pragma unroll
        for (int ni = 0; ni < 8; ++ni)
#pragma unroll
            for (int j = 0; j < 4; ++j) sacc[ni][j] = 0.0f;

        if (active) {
#pragma unroll
            for (int kb = 0; kb < 8; ++kb) {
                unsigned a0, a1, a2, a3;
                ldsm4(a0, a1, a2, a3,
                      qs_b + (unsigned)((wrow + a_r) * QLD + kb * 16 + a_c) * 2);
#pragma unroll
                for (int np = 0; np < 4; ++np) {
                    unsigned b0, b1, b2, b3;
                    ldsm4(b0, b1, b2, b3,
                          ks_b + (unsigned)((np * 16 + b_r) * QLD + kb * 16 + b_c) * 2);
                    mma_f16(sacc[2 * np],     a0, a1, a2, a3, b0, b1);
                    mma_f16(sacc[2 * np + 1], a0, a1, a2, a3, b2, b3);
                }
            }
        }

        cp_wait<0>();       // V(kt) landed
        __syncthreads();    // Ks consumed -> refill
        if (kt < ktmax) {
#pragma unroll
            for (int i = 0; i < 4; ++i) {
                int idx = tid + 256 * i; int row = idx >> 4; int c8 = (idx & 15) * 8;
                cp16(ks_b + (unsigned)(row * QLD + c8) * 2,
                     K + (size_t)((kt + 1) * 64 + row) * KVDIM + kvh * HD + c8);
            }
        }
        cp_commit();

        float corr0 = 1.0f, corr1 = 1.0f;
        if (active) {
            if (kt * 64 + 63 > qt * 128 + wrow) {
                const int cb = kt * 64 + 2 * tig;
#pragma unroll
                for (int ni = 0; ni < 8; ++ni) {
                    const int c0 = cb + 8 * ni, c1 = c0 + 1;
                    if (c0 > r0g) sacc[ni][0] = -1e30f;
                    if (c1 > r0g) sacc[ni][1] = -1e30f;
                    if (c0 > r1g) sacc[ni][2] = -1e30f;
                    if (c1 > r1g) sacc[ni][3] = -1e30f;
                }
            }
            float mx0 = -1e30f, mx1 = -1e30f;
#pragma unroll
            for (int ni = 0; ni < 8; ++ni) {
                mx0 = fmaxf(mx0, fmaxf(sacc[ni][0], sacc[ni][1]));
                mx1 = fmaxf(mx1, fmaxf(sacc[ni][2], sacc[ni][3]));
            }
            mx0 = fmaxf(mx0, __shfl_xor_sync(0xffffffffu, mx0, 1));
            mx0 = fmaxf(mx0, __shfl_xor_sync(0xffffffffu, mx0, 2));
            mx1 = fmaxf(mx1, __shfl_xor_sync(0xffffffffu, mx1, 1));
            mx1 = fmaxf(mx1, __shfl_xor_sync(0xffffffffu, mx1, 2));

            const float mn0 = fmaxf(m0, mx0);
            const float mn1 = fmaxf(m1, mx1);
            corr0 = __expf(m0 - mn0);
            corr1 = __expf(m1 - mn1);

            float s0 = 0.0f, s1 = 0.0f;
#pragma unroll
            for (int ni = 0; ni < 8; ++ni) {
                const int c0 = 8 * ni + 2 * tig;
                float p00 = __expf(sacc[ni][0] - mn0);
                float p01 = __expf(sacc[ni][1] - mn0);
                float p10 = __expf(sacc[ni][2] - mn1);
                float p11 = __expf(sacc[ni][3] - mn1);
                *(__half2*)&Pw[gid * PLD + c0]       = __floats2half2_rn(p00, p01);
                *(__half2*)&Pw[(gid + 8) * PLD + c0] = __floats2half2_rn(p10, p11);
                s0 += p00 + p01;
                s1 += p10 + p11;
            }
            s0 += __shfl_xor_sync(0xffffffffu, s0, 1);
            s0 += __shfl_xor_sync(0xffffffffu, s0, 2);
            s1 += __shfl_xor_sync(0xffffffffu, s1, 1);
            s1 += __shfl_xor_sync(0xffffffffu, s1, 2);

            m0 = mn0; m1 = mn1;
            l0 = l0 * corr0 + s0;
            l1 = l1 * corr1 + s1;
        }
        __syncwarp();

        if (active) {
#pragma unroll
            for (int ni = 0; ni < 16; ++ni) {
                oacc[ni][0] *= corr0; oacc[ni][1] *= corr0;
                oacc[ni][2] *= corr1; oacc[ni][3] *= corr1;
            }
#pragma unroll
            for (int kb = 0; kb < 4; ++kb) {
                unsigned a0, a1, a2, a3;
                ldsm4(a0, a1, a2, a3,
                      pw_b + (unsigned)(a_r * PLD + kb * 16 + a_c) * 2);
#pragma unroll
                for (int np = 0; np < 8; ++np) {
                    unsigned v0, v1, v2, v3;
                    ldsm4t(v0, v1, v2, v3,
                           vs_b + (unsigned)((kb * 16 + a_r) * QLD + np * 16 + a_c) * 2);
                    mma_f16(oacc[2 * np],     a0, a1, a2, a3, v0, v1);
                    mma_f16(oacc[2 * np + 1], a0, a1, a2, a3, v2, v3);
                }
            }
        }
        __syncthreads();    // Vs consumed -> refill
        if (kt < ktmax) {
#pragma unroll
            for (int i = 0; i < 4; ++i) {
                int idx = tid + 256 * i; int row = idx >> 4; int c8 = (idx & 15) * 8;
                cp16(vs_b + (unsigned)(row * QLD + c8) * 2,
                     V + (size_t)((kt + 1) * 64 + row) * KVDIM + kvh * HD + c8);
            }
        }
        cp_commit();
    }

    // ---- epilogue (half AO) ----
    const float li0 = 1.0f / l0;
    const float li1 = 1.0f / l1;
#pragma unroll
    for (int ni = 0; ni < 16; ++ni) {
        const int col = h * HD + 8 * ni + 2 * tig;
        *(__half2*)&Out[(size_t)r0g * HID + col] =
            __floats2half2_rn(oacc[ni][0] * li0, oacc[ni][1] * li0);
        *(__half2*)&Out[(size_t)r1g * HID + col] =
            __floats2half2_rn(oacc[ni][2] * li1, oacc[ni][3] * li1);
    }
}

// ============================================================
// launch
// ============================================================
extern "C" void kernel_launch(void* const* d_in, const int* in_sizes, int n_in,
                              void* d_out, int out_size)
{
    const float* hidden = (const float*)d_in[0];
    // d_in[1] = attention_mask: exactly causal -> applied analytically
    const float* q_w = (const float*)d_in[2];
    const float* q_b = (const float*)d_in[3];
    const float* k_w = (const float*)d_in[4];
    const float* k_b = (const float*)d_in[5];
    const float* v_w = (const float*)d_in[6];
    const float* v_b = (const float*)d_in[7];
    const float* o_w = (const float*)d_in[8];
    float* out = (float*)d_out;

    float *Qp, *Kp, *Vp;
    __half *Xh, *Wq, *Wk, *Wv, *Wo, *Qh, *Kh, *Vh, *AOh;
    cudaGetSymbolAddress((void**)&Qp,  g_Q);
    cudaGetSymbolAddress((void**)&Kp,  g_K);
    cudaGetSymbolAddress((void**)&Vp,  g_V);
    cudaGetSymbolAddress((void**)&Xh,  g_Xh);
    cudaGetSymbolAddress((void**)&Wq,  g_Wq);
    cudaGetSymbolAddress((void**)&Wk,  g_Wk);
    cudaGetSymbolAddress((void**)&Wv,  g_Wv);
    cudaGetSymbolAddress((void**)&Wo,  g_Wo);
    cudaGetSymbolAddress((void**)&Qh,  g_Qh);
    cudaGetSymbolAddress((void**)&Kh,  g_Kh);
    cudaGetSymbolAddress((void**)&Vh,  g_Vh);
    cudaGetSymbolAddress((void**)&AOh, g_AOh);

    // one-time fp16 conversions
    f32_to_f16<<<(S_LEN * HID / 4 + 255) / 256, 256>>>(hidden, Xh, S_LEN * HID);
    f32_to_f16<<<(HID * HID / 4 + 255) / 256, 256>>>(q_w, Wq, HID * HID);
    f32_to_f16<<<(KVDIM * HID / 4 + 255) / 256, 256>>>(k_w, Wk, KVDIM * HID);
    f32_to_f16<<<(KVDIM * HID / 4 + 255) / 256, 256>>>(v_w, Wv, KVDIM * HID);
    f32_to_f16<<<(HID * HID / 4 + 255) / 256, 256>>>(o_w, Wo, HID * HID);

    rope_table_kernel<<<(S_LEN * 64) / 256, 256>>>();

    // projections (fp16 in, float out for RoPE precision)
    gemm_f16<float><<<dim3(HID / 64, S_LEN / 128), 256>>>(
        Xh, Wq, q_b, Qp, S_LEN, HID, HID);
    gemm_f16<float><<<dim3(KVDIM / 64, S_LEN / 128), 256>>>(
        Xh, Wk, k_b, Kp, S_LEN, KVDIM, HID);
    gemm_f16<float><<<dim3(KVDIM / 64, S_LEN / 128), 256>>>(
        Xh, Wv, v_b, Vp, S_LEN, KVDIM, HID);

    // RoPE + fp16 conversion (Q scaled by 1/sqrt(HD))
    rope_half_kernel<<<S_LEN, 256>>>(Qp, Kp, Vp, Qh, Kh, Vh);

    // flash attention (fp16 in, fp16 AO out)
    int smem = (128 * QLD + 64 * QLD + 64 * QLD + 8 * 16 * PLD) * (int)sizeof(__half);
    cudaFuncSetAttribute(flash_f16,
                         cudaFuncAttributeMaxDynamicSharedMemorySize, smem);
    flash_f16<<<dim3(S_LEN / 128, NH), 256, smem>>>(Qh, Kh, Vh, AOh);

    // output projection (fp16 in, float out)
    gemm_f16<float><<<dim3(HID / 64, S_LEN / 128), 256>>>(
        AOh, Wo, nullptr, out, S_LEN, HID, HID);
}